// round 14
// baseline (speedup 1.0000x reference)
#include <cuda_runtime.h>
#include <cuda_fp16.h>
#include <cstdint>
#include <math.h>

// ---------------- problem constants ----------------
#define Bq    4
#define LIN   13294
#define MTOK  (Bq * LIN)      // 53176
#define DMODEL 256
#define NHEAD 8
#define NLVL  4
#define NPTS  4
#define DH    32
#define DFF   1024

// ---------------- scratch (device globals) ----------------
__device__ __half g_qh   [(size_t)MTOK * DMODEL];
__device__ __half g_value[(size_t)MTOK * DMODEL];   // row-major [tok][256]
__device__ __half g_offs [(size_t)MTOK * DMODEL];   // fp16 now
__device__ float  g_aw   [(size_t)MTOK * 128];      // raw logits (fp32)
__device__ __half g_msdah[(size_t)MTOK * DMODEL];
__device__ __half g_xh   [(size_t)MTOK * DMODEL];
__device__ __half g_ffh  [(size_t)MTOK * DFF];
// weights: Wt[N, K] fp16 K-major
__device__ __half g_wt_proj[640 * 256];
__device__ __half g_wt_out [256 * 256];
__device__ __half g_wt_ff1 [1024 * 256];
__device__ __half g_wt_ff2 [256 * 1024];
__device__ float  g_bias_proj[640];

// ---------------- helpers ----------------
__device__ __forceinline__ uint32_t smem_u32(const void* p) {
    uint32_t a;
    asm("{ .reg .u64 t; cvta.to.shared.u64 t, %1; cvt.u32.u64 %0, t; }" : "=r"(a) : "l"(p));
    return a;
}
#define CP_ASYNC16(dst, src) \
    asm volatile("cp.async.cg.shared.global [%0], [%1], 16;\n" :: "r"(dst), "l"(src) : "memory")
#define CP_COMMIT() asm volatile("cp.async.commit_group;\n" ::: "memory")
#define CP_WAIT(n)  asm volatile("cp.async.wait_group %0;\n" :: "n"(n) : "memory")

__device__ __forceinline__ void ldmatrix_x4(uint32_t& r0, uint32_t& r1, uint32_t& r2, uint32_t& r3, uint32_t addr) {
    asm volatile("ldmatrix.sync.aligned.m8n8.x4.shared.b16 {%0,%1,%2,%3}, [%4];"
                 : "=r"(r0), "=r"(r1), "=r"(r2), "=r"(r3) : "r"(addr));
}
__device__ __forceinline__ void mma_f16(float* c, const uint32_t* a, const uint32_t* b) {
    asm volatile("mma.sync.aligned.m16n8k16.row.col.f32.f16.f16.f32 "
                 "{%0,%1,%2,%3}, {%4,%5,%6,%7}, {%8,%9}, {%0,%1,%2,%3};"
                 : "+f"(c[0]), "+f"(c[1]), "+f"(c[2]), "+f"(c[3])
                 : "r"(a[0]), "r"(a[1]), "r"(a[2]), "r"(a[3]), "r"(b[0]), "r"(b[1]));
}

#define PADS 40
#define NSTAGE 4

// ================= gemm_mma: 128x64 tile, 3 CTAs/SM ========================
// 256 threads, 8 warps (4 wm x 2 wn), warp tile 32x32, pair-buffered cp.async.
// mode 1: Ch fp16 [M,N].
// mode 2: cols 0-255 -> Ch fp16 (value,256); 256-511 -> C2h fp16 (offs,256);
//         512-639 -> C3 fp32 (aw,128). bias by global col.
#define A2_ST (128 * PADS * 2)     // 10240 B per A stage
#define B2_ST (64 * PADS * 2)      // 5120 B per B stage
#define GEMM_SMEM (NSTAGE * (A2_ST + B2_ST))   // 61440 bytes

__global__ __launch_bounds__(256, 3)
void gemm_mma(const __half* __restrict__ A, int lda,
              const __half* __restrict__ B, int ldb,
              const float* __restrict__ bias,
              float* __restrict__ Cf, __half* __restrict__ Ch,
              __half* __restrict__ C2h, float* __restrict__ C3,
              int M, int K, int N, int relu, int mode)
{
    extern __shared__ __align__(16) __half dynsmem[];

    const int tid  = threadIdx.x;
    const int wid  = tid >> 5;
    const int lane = tid & 31;
    const int wm   = wid & 3;
    const int wn   = wid >> 2;          // 0..1
    const int row0 = blockIdx.y * 128;
    const int col0 = blockIdx.x * 64;

    const uint32_t sbase = smem_u32(dynsmem);
    const uint32_t sbB = sbase + NSTAGE * A2_ST;
    const int NC2 = K >> 6;

    float acc[2][4][4];
#pragma unroll
    for (int i = 0; i < 2; i++)
#pragma unroll
        for (int j = 0; j < 4; j++)
#pragma unroll
            for (int t = 0; t < 4; t++) acc[i][j][t] = 0.f;

#define LOAD_STAGE(buf, cc) do {                                              \
        int _kc = (cc) << 5;                                                  \
        uint32_t _dA = sbase + (buf) * A2_ST;                                 \
        uint32_t _dB = sbB + (buf) * B2_ST;                                   \
        _Pragma("unroll")                                                     \
        for (int _i = 0; _i < 2; ++_i) {                                      \
            int _c = tid + _i * 256;                                          \
            int _r = _c >> 2, _k8 = _c & 3;                                   \
            int _gr = row0 + _r; if (_gr >= M) _gr = M - 1;                   \
            CP_ASYNC16(_dA + (_r * PADS + _k8 * 8) * 2,                       \
                       A + (size_t)_gr * lda + _kc + _k8 * 8);                \
        }                                                                     \
        {                                                                     \
            int _r = tid >> 2, _k8 = tid & 3;                                 \
            CP_ASYNC16(_dB + (_r * PADS + _k8 * 8) * 2,                       \
                       B + (size_t)(col0 + _r) * ldb + _kc + _k8 * 8);        \
        }                                                                     \
    } while (0)

    LOAD_STAGE(0, 0);
    LOAD_STAGE(1, 1);
    CP_COMMIT();

    for (int c = 0; c < NC2; ++c) {
        CP_WAIT(0);
        __syncthreads();

        if (c + 1 < NC2) {
            const int pb = ((c + 1) & 1) << 1;
            LOAD_STAGE(pb, 2 * (c + 1));
            LOAD_STAGE(pb + 1, 2 * (c + 1) + 1);
        }
        CP_COMMIT();

        const int cb = (c & 1) << 1;
#pragma unroll
        for (int hs = 0; hs < 2; hs++) {
            const uint32_t baseA = sbase + (cb + hs) * A2_ST;
            const uint32_t baseB = sbB + (cb + hs) * B2_ST;
#pragma unroll
            for (int kk = 0; kk < 32; kk += 16) {
                uint32_t a[2][4];
#pragma unroll
                for (int mt = 0; mt < 2; mt++) {
                    int r = wm * 32 + mt * 16 + (lane & 15);
                    int kc = kk + ((lane & 16) ? 8 : 0);
                    ldmatrix_x4(a[mt][0], a[mt][1], a[mt][2], a[mt][3],
                                baseA + (r * PADS + kc) * 2);
                }
                uint32_t b[4][2];
#pragma unroll
                for (int np = 0; np < 2; np++) {
                    int n = wn * 32 + np * 16 + (lane & 7) + ((lane & 16) ? 8 : 0);
                    int kc = kk + ((lane & 8) ? 8 : 0);
                    ldmatrix_x4(b[2 * np][0], b[2 * np][1], b[2 * np + 1][0], b[2 * np + 1][1],
                                baseB + (n * PADS + kc) * 2);
                }
#pragma unroll
                for (int mt = 0; mt < 2; mt++)
#pragma unroll
                    for (int nt = 0; nt < 4; nt++)
                        mma_f16(acc[mt][nt], a[mt], b[nt]);
            }
        }
    }

    // ---- epilogue ----
    float* outf = Cf;
    __half* outh = Ch;
    int ostride = N, coff = 0;
    int write_half = (mode == 1);
    if (mode == 2) {
        if (col0 < 256)      { outh = Ch;  ostride = 256; coff = 0;   write_half = 1; }
        else if (col0 < 512) { outh = C2h; ostride = 256; coff = 256; write_half = 1; }
        else                 { outf = C3;  ostride = 128; coff = 512; }
    }

#pragma unroll
    for (int mt = 0; mt < 2; mt++) {
#pragma unroll
        for (int half_i = 0; half_i < 2; half_i++) {
            int r = row0 + wm * 32 + mt * 16 + (lane >> 2) + half_i * 8;
            if (r >= M) continue;
#pragma unroll
            for (int nt = 0; nt < 4; nt++) {
                int cidx = col0 + wn * 32 + nt * 8 + (lane & 3) * 2;
                float v0 = acc[mt][nt][half_i * 2 + 0] + bias[cidx];
                float v1 = acc[mt][nt][half_i * 2 + 1] + bias[cidx + 1];
                if (relu) { v0 = fmaxf(v0, 0.f); v1 = fmaxf(v1, 0.f); }
                if (write_half) {
                    __half2 hv;
                    hv.x = __float2half_rn(v0);
                    hv.y = __float2half_rn(v1);
                    *reinterpret_cast<__half2*>(outh + (size_t)r * ostride + (cidx - coff)) = hv;
                } else {
                    float2 o = make_float2(v0, v1);
                    *reinterpret_cast<float2*>(outf + (size_t)r * ostride + (cidx - coff)) = o;
                }
            }
        }
    }
#undef LOAD_STAGE
}

// ---------------- GEMM + residual(fp16) + LayerNorm fused (N = 256) --------
#define A_ST (128 * PADS * 2)
#define B_ST (256 * PADS * 2)
#define GEMMLN_SMEM (NSTAGE * (A_ST + B_ST))   // 122880 bytes

__global__ __launch_bounds__(512, 1)
void gemm_ln(const __half* __restrict__ A, int lda,
             const __half* __restrict__ B,
             const float* __restrict__ bias,
             const __half* __restrict__ resid,
             const float* __restrict__ lng, const float* __restrict__ lnb,
             float* __restrict__ out, __half* __restrict__ outh,
             int M, int K)
{
    extern __shared__ __align__(16) __half dynsmem[];

    const int tid  = threadIdx.x;
    const int wid  = tid >> 5;
    const int lane = tid & 31;
    const int wm   = wid & 3;
    const int wn   = wid >> 2;
    const int row0 = blockIdx.y * 128;

    const uint32_t sbase = smem_u32(dynsmem);
    const uint32_t sbB = sbase + NSTAGE * A_ST;
    const int NC2 = K >> 6;

    float acc[2][8][4];
#pragma unroll
    for (int i = 0; i < 2; i++)
#pragma unroll
        for (int j = 0; j < 8; j++)
#pragma unroll
            for (int t = 0; t < 4; t++) acc[i][j][t] = 0.f;

#define LOAD_STAGE_LN(buf, cc) do {                                           \
        int _kc = (cc) << 5;                                                  \
        uint32_t _dA = sbase + (buf) * A_ST;                                  \
        uint32_t _dB = sbB + (buf) * B_ST;                                    \
        {                                                                     \
            int _r = tid >> 2, _k8 = tid & 3;                                 \
            int _gr = row0 + _r; if (_gr >= M) _gr = M - 1;                   \
            CP_ASYNC16(_dA + (_r * PADS + _k8 * 8) * 2,                       \
                       A + (size_t)_gr * lda + _kc + _k8 * 8);                \
        }                                                                     \
        _Pragma("unroll")                                                     \
        for (int _i = 0; _i < 2; ++_i) {                                      \
            int _c = tid + _i * 512;                                          \
            int _r = _c >> 2, _k8 = _c & 3;                                   \
            CP_ASYNC16(_dB + (_r * PADS + _k8 * 8) * 2,                       \
                       B + (size_t)_r * K + _kc + _k8 * 8);                   \
        }                                                                     \
    } while (0)

    LOAD_STAGE_LN(0, 0);
    LOAD_STAGE_LN(1, 1);
    CP_COMMIT();

    for (int c = 0; c < NC2; ++c) {
        CP_WAIT(0);
        __syncthreads();

        if (c + 1 < NC2) {
            const int pb = ((c + 1) & 1) << 1;
            LOAD_STAGE_LN(pb, 2 * (c + 1));
            LOAD_STAGE_LN(pb + 1, 2 * (c + 1) + 1);
        }
        CP_COMMIT();

        const int cb = (c & 1) << 1;
#pragma unroll
        for (int hs = 0; hs < 2; hs++) {
            const uint32_t baseA = sbase + (cb + hs) * A_ST;
            const uint32_t baseB = sbB + (cb + hs) * B_ST;
#pragma unroll
            for (int kk = 0; kk < 32; kk += 16) {
                uint32_t a[2][4];
#pragma unroll
                for (int mt = 0; mt < 2; mt++) {
                    int r = wm * 32 + mt * 16 + (lane & 15);
                    int kc = kk + ((lane & 16) ? 8 : 0);
                    ldmatrix_x4(a[mt][0], a[mt][1], a[mt][2], a[mt][3],
                                baseA + (r * PADS + kc) * 2);
                }
                uint32_t b[8][2];
#pragma unroll
                for (int np = 0; np < 4; np++) {
                    int n = wn * 64 + np * 16 + (lane & 7) + ((lane & 16) ? 8 : 0);
                    int kc = kk + ((lane & 8) ? 8 : 0);
                    ldmatrix_x4(b[2 * np][0], b[2 * np][1], b[2 * np + 1][0], b[2 * np + 1][1],
                                baseB + (n * PADS + kc) * 2);
                }
#pragma unroll
                for (int mt = 0; mt < 2; mt++)
#pragma unroll
                    for (int nt = 0; nt < 8; nt++)
                        mma_f16(acc[mt][nt], a[mt], b[nt]);
            }
        }
    }

    // ---- fused epilogue: bias + fp16 residual + per-row LayerNorm ----
    __syncthreads();
    float* red = reinterpret_cast<float*>(dynsmem);

#pragma unroll
    for (int mt = 0; mt < 2; mt++) {
#pragma unroll
        for (int hf = 0; hf < 2; hf++) {
            int lr = wm * 32 + mt * 16 + (lane >> 2) + hf * 8;
            int r = row0 + lr;
            int rc = (r < M) ? r : (M - 1);
            float s1 = 0.f, s2 = 0.f;
#pragma unroll
            for (int nt = 0; nt < 8; nt++) {
                int cidx = wn * 64 + nt * 8 + (lane & 3) * 2;
                __half2 rh = *reinterpret_cast<const __half2*>(resid + (size_t)rc * 256 + cidx);
                float2 res = __half22float2(rh);
                float2 bv = *reinterpret_cast<const float2*>(bias + cidx);
                float v0 = acc[mt][nt][hf * 2 + 0] + bv.x + res.x;
                float v1 = acc[mt][nt][hf * 2 + 1] + bv.y + res.y;
                acc[mt][nt][hf * 2 + 0] = v0;
                acc[mt][nt][hf * 2 + 1] = v1;
                s1 += v0 + v1;
                s2 += v0 * v0 + v1 * v1;
            }
            s1 += __shfl_xor_sync(0xffffffffu, s1, 1);
            s2 += __shfl_xor_sync(0xffffffffu, s2, 1);
            s1 += __shfl_xor_sync(0xffffffffu, s1, 2);
            s2 += __shfl_xor_sync(0xffffffffu, s2, 2);
            if ((lane & 3) == 0) {
                red[(wn * 128 + lr) * 2 + 0] = s1;
                red[(wn * 128 + lr) * 2 + 1] = s2;
            }
        }
    }
    __syncthreads();

#pragma unroll
    for (int mt = 0; mt < 2; mt++) {
#pragma unroll
        for (int hf = 0; hf < 2; hf++) {
            int lr = wm * 32 + mt * 16 + (lane >> 2) + hf * 8;
            int r = row0 + lr;
            if (r >= M) continue;
            float t1 = red[(0 * 128 + lr) * 2 + 0] + red[(1 * 128 + lr) * 2 + 0]
                     + red[(2 * 128 + lr) * 2 + 0] + red[(3 * 128 + lr) * 2 + 0];
            float t2 = red[(0 * 128 + lr) * 2 + 1] + red[(1 * 128 + lr) * 2 + 1]
                     + red[(2 * 128 + lr) * 2 + 1] + red[(3 * 128 + lr) * 2 + 1];
            float mean = t1 * (1.f / 256.f);
            float var = t2 * (1.f / 256.f) - mean * mean;
            float inv = rsqrtf(var + 1e-5f);
#pragma unroll
            for (int nt = 0; nt < 8; nt++) {
                int cidx = wn * 64 + nt * 8 + (lane & 3) * 2;
                float2 gv = *reinterpret_cast<const float2*>(lng + cidx);
                float2 bv = *reinterpret_cast<const float2*>(lnb + cidx);
                float o0 = (acc[mt][nt][hf * 2 + 0] - mean) * inv * gv.x + bv.x;
                float o1 = (acc[mt][nt][hf * 2 + 1] - mean) * inv * gv.y + bv.y;
                if (out)
                    *reinterpret_cast<float2*>(out + (size_t)r * 256 + cidx) = make_float2(o0, o1);
                if (outh) {
                    __half2 hv;
                    hv.x = __float2half_rn(o0);
                    hv.y = __float2half_rn(o1);
                    *reinterpret_cast<__half2*>(outh + (size_t)r * 256 + cidx) = hv;
                }
            }
        }
    }
#undef LOAD_STAGE_LN
}

// ---------------- fused weight prep + qh = fp16(src + pos) -----------------
__device__ __forceinline__ void wtr1(const float* __restrict__ W, __half* __restrict__ Wt,
                                     int K_, int N_, int i)
{
    int k = i / N_, n = i % N_;
    Wt[(size_t)n * K_ + k] = __float2half_rn(W[i]);
}

#define PREP_ITEMS 754304
#define ADD_ITEMS  (MTOK * DMODEL / 4)
#define PA_TOTAL   (PREP_ITEMS + ADD_ITEMS)

__global__ void prep_add_kernel(const float* __restrict__ vW, const float* __restrict__ oW,
                                const float* __restrict__ aW, const float* __restrict__ uW,
                                const float* __restrict__ f1W, const float* __restrict__ f2W,
                                const float* __restrict__ vb, const float* __restrict__ ob,
                                const float* __restrict__ ab,
                                __half* __restrict__ wtp, __half* __restrict__ wtu,
                                __half* __restrict__ wtf1, __half* __restrict__ wtf2,
                                float* __restrict__ biasp,
                                const float* __restrict__ srca, const float* __restrict__ posb,
                                __half* __restrict__ qh)
{
    int i = blockIdx.x * blockDim.x + threadIdx.x;
    if (i >= PREP_ITEMS) {
        int t = i - PREP_ITEMS;
        if (t >= ADD_ITEMS) return;
        float4 x = reinterpret_cast<const float4*>(srca)[t];
        float4 y = reinterpret_cast<const float4*>(posb)[t];
        x.x += y.x; x.y += y.y; x.z += y.z; x.w += y.w;
        __half2 h0 = __floats2half2_rn(x.x, x.y);
        __half2 h1 = __floats2half2_rn(x.z, x.w);
        uint2 hp;
        hp.x = *reinterpret_cast<uint32_t*>(&h0);
        hp.y = *reinterpret_cast<uint32_t*>(&h1);
        reinterpret_cast<uint2*>(qh)[t] = hp;
        return;
    }
    if (i < 65536)       { wtr1(vW, wtp, 256, 256, i); return; }
    i -= 65536;
    if (i < 65536)       { wtr1(oW, wtp + 256 * 256, 256, 256, i); return; }
    i -= 65536;
    if (i < 32768)       { wtr1(aW, wtp + 512 * 256, 256, 128, i); return; }
    i -= 32768;
    if (i < 65536)       { wtr1(uW, wtu, 256, 256, i); return; }
    i -= 65536;
    if (i < 262144)      { wtr1(f1W, wtf1, 256, 1024, i); return; }
    i -= 262144;
    if (i < 262144)      { wtr1(f2W, wtf2, 1024, 256, i); return; }
    i -= 262144;
    if (i < 256)         { biasp[i] = vb[i]; return; }
    if (i < 512)         { biasp[i] = ob[i - 256]; return; }
    if (i < 640)         { biasp[i] = ab[i - 512]; return; }
}

// ---------------- MSDA: fused softmax + float4 gathers (row-major value) ---
__global__ __launch_bounds__(256)
void msda_kernel(const __half* __restrict__ value, const __half* __restrict__ offs,
                 const float* __restrict__ aw, const float* __restrict__ ref,
                 const int* __restrict__ shapes, const int* __restrict__ starts,
                 __half* __restrict__ outh)
{
    const int tok = blockIdx.x;
    const int h = threadIdx.x >> 5;
    const int lane = threadIdx.x & 31;
    const int j = lane & 15;
    const int b = tok / LIN;
    const int l = j >> 2;

    const int Hl = shapes[l * 2 + 0];
    const int Wl = shapes[l * 2 + 1];
    const int st = starts[l];
    const float fW = (float)Wl, fH = (float)Hl;
    const float rx = ref[(size_t)tok * 8 + l * 2 + 0];
    const float ry = ref[(size_t)tok * 8 + l * 2 + 1];
    __half2 offh = *reinterpret_cast<const __half2*>(offs + (size_t)tok * 256 + h * 32 + 2 * j);
    float2 off = __half22float2(offh);

    float logit = aw[(size_t)tok * 128 + h * 16 + j];
    float m = logit;
#pragma unroll
    for (int o = 8; o; o >>= 1) m = fmaxf(m, __shfl_xor_sync(0xffffffffu, m, o, 16));
    float e = expf(logit - m);
    float s = e;
#pragma unroll
    for (int o = 8; o; o >>= 1) s += __shfl_xor_sync(0xffffffffu, s, o, 16);
    float wgt = e / s;

    float x = (rx + off.x / fW) * fW - 0.5f;
    float y = (ry + off.y / fH) * fH - 0.5f;
    float x0f = floorf(x), y0f = floorf(y);
    float dx = x - x0f, dy = y - y0f;
    int x0 = (int)x0f, y0 = (int)y0f;
    int x1 = x0 + 1, y1 = y0 + 1;

    bool xv0 = (x0 >= 0) & (x0 < Wl);
    bool xv1 = (x1 >= 0) & (x1 < Wl);
    bool yv0 = (y0 >= 0) & (y0 < Hl);
    bool yv1 = (y1 >= 0) & (y1 < Hl);

    float w00 = (xv0 && yv0) ? wgt * (1.f - dx) * (1.f - dy) : 0.f;
    float w10 = (xv1 && yv0) ? wgt * dx * (1.f - dy) : 0.f;
    float w01 = (xv0 && yv1) ? wgt * (1.f - dx) * dy : 0.f;
    float w11 = (xv1 && yv1) ? wgt * dx * dy : 0.f;

    int cx0 = min(max(x0, 0), Wl - 1), cx1 = min(max(x1, 0), Wl - 1);
    int cy0 = min(max(y0, 0), Hl - 1), cy1 = min(max(y1, 0), Hl - 1);
    const int base = b * LIN + st;
    int i00 = base + cy0 * Wl + cx0;
    int i10 = base + cy0 * Wl + cx1;
    int i01 = base + cy1 * Wl + cx0;
    int i11 = base + cy1 * Wl + cx1;

    const int g = lane >> 2;
    const int c4 = lane & 3;
    const __half* vch = value + h * DH + c4 * 8;
    float acc[8] = {0.f, 0.f, 0.f, 0.f, 0.f, 0.f, 0.f, 0.f};

#pragma unroll
    for (int p = 0; p < 2; p++) {
        const int pt = p * 8 + g;
        int a00 = __shfl_sync(0xffffffffu, i00, pt);
        int a10 = __shfl_sync(0xffffffffu, i10, pt);
        int a01 = __shfl_sync(0xffffffffu, i01, pt);
        int a11 = __shfl_sync(0xffffffffu, i11, pt);
        float u00 = __shfl_sync(0xffffffffu, w00, pt);
        float u10 = __shfl_sync(0xffffffffu, w10, pt);
        float u01 = __shfl_sync(0xffffffffu, w01, pt);
        float u11 = __shfl_sync(0xffffffffu, w11, pt);

        uint4 r00 = *reinterpret_cast<const uint4*>(vch + (size_t)a00 * DMODEL);
        uint4 r10 = *reinterpret_cast<const uint4*>(vch + (size_t)a10 * DMODEL);
        uint4 r01 = *reinterpret_cast<const uint4*>(vch + (size_t)a01 * DMODEL);
        uint4 r11 = *reinterpret_cast<const uint4*>(vch + (size_t)a11 * DMODEL);

#define ACC8(rv, u) do {                                                      \
        const __half2* _h = reinterpret_cast<const __half2*>(&(rv));          \
        _Pragma("unroll")                                                     \
        for (int _k = 0; _k < 4; _k++) {                                      \
            float2 _f = __half22float2(_h[_k]);                               \
            acc[2 * _k + 0] = fmaf(u, _f.x, acc[2 * _k + 0]);                 \
            acc[2 * _k + 1] = fmaf(u, _f.y, acc[2 * _k + 1]);                 \
        } } while (0)

        ACC8(r00, u00);
        ACC8(r10, u10);
        ACC8(r01, u01);
        ACC8(r11, u11);
#undef ACC8
    }

#pragma unroll
    for (int o = 4; o <= 16; o <<= 1) {
#pragma unroll
        for (int k = 0; k < 8; k++)
            acc[k] += __shfl_xor_sync(0xffffffffu, acc[k], o);
    }

    if (lane < 4) {
        __half2 h0 = __floats2half2_rn(acc[0], acc[1]);
        __half2 h1 = __floats2half2_rn(acc[2], acc[3]);
        __half2 h2 = __floats2half2_rn(acc[4], acc[5]);
        __half2 h3 = __floats2half2_rn(acc[6], acc[7]);
        uint4 o;
        o.x = *reinterpret_cast<uint32_t*>(&h0);
        o.y = *reinterpret_cast<uint32_t*>(&h1);
        o.z = *reinterpret_cast<uint32_t*>(&h2);
        o.w = *reinterpret_cast<uint32_t*>(&h3);
        *reinterpret_cast<uint4*>(outh + (size_t)tok * DMODEL + h * DH + lane * 8) = o;
    }
}

// ---------------- launch ----------------
extern "C" void kernel_launch(void* const* d_in, const int* in_sizes, int n_in,
                              void* d_out, int out_size)
{
    const float* src    = (const float*)d_in[0];
    const float* pos    = (const float*)d_in[1];
    const float* refpts = (const float*)d_in[2];
    const int*   shapes = (const int*)  d_in[3];
    const int*   starts = (const int*)  d_in[4];
    const float* value_w = (const float*)d_in[5];
    const float* value_b = (const float*)d_in[6];
    const float* offs_w  = (const float*)d_in[7];
    const float* offs_b  = (const float*)d_in[8];
    const float* attn_w  = (const float*)d_in[9];
    const float* attn_b  = (const float*)d_in[10];
    const float* out_w   = (const float*)d_in[11];
    const float* out_b   = (const float*)d_in[12];
    const float* ln1_g   = (const float*)d_in[13];
    const float* ln1_b   = (const float*)d_in[14];
    const float* ff1_w   = (const float*)d_in[15];
    const float* ff1_b   = (const float*)d_in[16];
    const float* ff2_w   = (const float*)d_in[17];
    const float* ff2_b   = (const float*)d_in[18];
    const float* ln2_g   = (const float*)d_in[19];
    const float* ln2_b   = (const float*)d_in[20];
    float* outp = (float*)d_out;

    float *aw, *biasp;
    __half *qh, *value, *offs, *msdah, *xh, *ffh;
    __half *wtp, *wtu, *wtf1, *wtf2;
    cudaGetSymbolAddress((void**)&qh,    g_qh);
    cudaGetSymbolAddress((void**)&value, g_value);
    cudaGetSymbolAddress((void**)&offs,  g_offs);
    cudaGetSymbolAddress((void**)&aw,    g_aw);
    cudaGetSymbolAddress((void**)&msdah, g_msdah);
    cudaGetSymbolAddress((void**)&xh,    g_xh);
    cudaGetSymbolAddress((void**)&ffh,   g_ffh);
    cudaGetSymbolAddress((void**)&wtp,   g_wt_proj);
    cudaGetSymbolAddress((void**)&wtu,   g_wt_out);
    cudaGetSymbolAddress((void**)&wtf1,  g_wt_ff1);
    cudaGetSymbolAddress((void**)&wtf2,  g_wt_ff2);
    cudaGetSymbolAddress((void**)&biasp, g_bias_proj);

    cudaFuncSetAttribute(gemm_mma, cudaFuncAttributeMaxDynamicSharedMemorySize, GEMM_SMEM);
    cudaFuncSetAttribute(gemm_ln, cudaFuncAttributeMaxDynamicSharedMemorySize, GEMMLN_SMEM);

    const int M = MTOK;
    const int gy = (M + 127) / 128;

    // 0. fused weight prep + qh = fp16(src + pos)
    prep_add_kernel<<<(PA_TOTAL + 255) / 256, 256>>>(value_w, offs_w, attn_w, out_w, ff1_w, ff2_w,
                                                     value_b, offs_b, attn_b,
                                                     wtp, wtu, wtf1, wtf2, biasp,
                                                     src, pos, qh);

    // 1. fused projections: [value(fp16) | offs(fp16) | aw(fp32)] = qh @ Wp^T
    gemm_mma<<<dim3(10, gy), 256, GEMM_SMEM>>>(qh, 256, wtp, 256, biasp,
                                               nullptr, value, offs, aw, M, 256, 640, 0, 2);

    // 2. deformable sampling with fused softmax
    msda_kernel<<<M, 256>>>(value, offs, aw, refpts, shapes, starts, msdah);

    // 3. xh = fp16(LN(qh + msda @ out_w + out_b))   [fused GEMM+LN]
    gemm_ln<<<dim3(1, gy), 512, GEMMLN_SMEM>>>(msdah, 256, wtu, out_b,
                                               qh, ln1_g, ln1_b, nullptr, xh, M, 256);

    // 4. ffh = relu(xh @ ff1_w + ff1_b) -> fp16
    gemm_mma<<<dim3(16, gy), 256, GEMM_SMEM>>>(xh, 256, wtf1, 256, ff1_b,
                                               nullptr, ffh, nullptr, nullptr, M, 256, 1024, 1, 1);

    // 5. out = LN(xh + ffh @ ff2_w + ff2_b)   [fused GEMM+LN]
    gemm_ln<<<dim3(1, gy), 512, GEMMLN_SMEM>>>(ffh, 1024, wtf2, ff2_b,
                                               xh, ln2_g, ln2_b, outp, nullptr, M, 1024);
}

// round 15
// speedup vs baseline: 1.0581x; 1.0581x over previous
#include <cuda_runtime.h>
#include <cuda_fp16.h>
#include <cstdint>
#include <math.h>

// ---------------- problem constants ----------------
#define Bq    4
#define LIN   13294
#define MTOK  (Bq * LIN)      // 53176
#define DMODEL 256
#define NHEAD 8
#define NLVL  4
#define NPTS  4
#define DH    32
#define DFF   1024

// ---------------- scratch (device globals) ----------------
__device__ __half g_qh   [(size_t)MTOK * DMODEL];
__device__ __half g_value[(size_t)MTOK * DMODEL];   // row-major [tok][256]
__device__ __half g_offs [(size_t)MTOK * DMODEL];   // fp16
__device__ float  g_aw   [(size_t)MTOK * 128];      // raw logits (fp32)
__device__ __half g_msdah[(size_t)MTOK * DMODEL];
__device__ __half g_xh   [(size_t)MTOK * DMODEL];
__device__ __half g_ffh  [(size_t)MTOK * DFF];
// weights: Wt[N, K] fp16 K-major
__device__ __half g_wt_proj[640 * 256];
__device__ __half g_wt_out [256 * 256];
__device__ __half g_wt_ff1 [1024 * 256];
__device__ __half g_wt_ff2 [256 * 1024];
__device__ float  g_bias_proj[640];

// ---------------- helpers ----------------
__device__ __forceinline__ uint32_t smem_u32(const void* p) {
    uint32_t a;
    asm("{ .reg .u64 t; cvta.to.shared.u64 t, %1; cvt.u32.u64 %0, t; }" : "=r"(a) : "l"(p));
    return a;
}
#define CP_ASYNC16(dst, src) \
    asm volatile("cp.async.cg.shared.global [%0], [%1], 16;\n" :: "r"(dst), "l"(src) : "memory")
#define CP_COMMIT() asm volatile("cp.async.commit_group;\n" ::: "memory")
#define CP_WAIT(n)  asm volatile("cp.async.wait_group %0;\n" :: "n"(n) : "memory")

__device__ __forceinline__ void ldmatrix_x4(uint32_t& r0, uint32_t& r1, uint32_t& r2, uint32_t& r3, uint32_t addr) {
    asm volatile("ldmatrix.sync.aligned.m8n8.x4.shared.b16 {%0,%1,%2,%3}, [%4];"
                 : "=r"(r0), "=r"(r1), "=r"(r2), "=r"(r3) : "r"(addr));
}
__device__ __forceinline__ void mma_f16(float* c, const uint32_t* a, const uint32_t* b) {
    asm volatile("mma.sync.aligned.m16n8k16.row.col.f32.f16.f16.f32 "
                 "{%0,%1,%2,%3}, {%4,%5,%6,%7}, {%8,%9}, {%0,%1,%2,%3};"
                 : "+f"(c[0]), "+f"(c[1]), "+f"(c[2]), "+f"(c[3])
                 : "r"(a[0]), "r"(a[1]), "r"(a[2]), "r"(a[3]), "r"(b[0]), "r"(b[1]));
}

#define PADS 40
#define STAGE_ELEMS (128 * PADS)
#define NSTAGE 4
#define GEMM_SMEM (2 * NSTAGE * STAGE_ELEMS * 2)   // 81920 bytes

// ---------------- fp16 warp-MMA GEMM (pair-buffered) — proj / ff1 ----------
// 128x128 tile, 8 warps (4 wm x 2 wn, warp tile 32x64).
// mode 1: Ch fp16 [M,N].
// mode 2: cols 0-255 -> Ch fp16 (value,256); 256-511 -> C2h fp16 (offs,256);
//         512-639 -> C3 fp32 (aw,128). bias by global col.
__global__ __launch_bounds__(256, 2)
void gemm_mma(const __half* __restrict__ A, int lda,
              const __half* __restrict__ B, int ldb,
              const float* __restrict__ bias,
              float* __restrict__ Cf, __half* __restrict__ Ch,
              __half* __restrict__ C2h, float* __restrict__ C3,
              int M, int K, int N, int relu, int mode)
{
    extern __shared__ __align__(16) __half dynsmem[];

    const int tid  = threadIdx.x;
    const int wid  = tid >> 5;
    const int lane = tid & 31;
    const int wm   = wid & 3;
    const int wn   = wid >> 2;
    const int row0 = blockIdx.y * 128;
    const int col0 = blockIdx.x * 128;

    const uint32_t sbase = smem_u32(dynsmem);
    const int NC2 = K >> 6;

    float acc[2][8][4];
#pragma unroll
    for (int i = 0; i < 2; i++)
#pragma unroll
        for (int j = 0; j < 8; j++)
#pragma unroll
            for (int t = 0; t < 4; t++) acc[i][j][t] = 0.f;

#define LOAD_STAGE(buf, cc) do {                                              \
        int _kc = (cc) << 5;                                                  \
        uint32_t _dA = sbase + (buf) * (STAGE_ELEMS * 2);                     \
        uint32_t _dB = sbase + (NSTAGE + (buf)) * (STAGE_ELEMS * 2);          \
        _Pragma("unroll")                                                     \
        for (int _i = 0; _i < 2; ++_i) {                                      \
            int _c = tid + _i * 256;                                          \
            int _r = _c >> 2, _k8 = _c & 3;                                   \
            int _gr = row0 + _r; if (_gr >= M) _gr = M - 1;                   \
            CP_ASYNC16(_dA + (_r * PADS + _k8 * 8) * 2,                       \
                       A + (size_t)_gr * lda + _kc + _k8 * 8);                \
        }                                                                     \
        _Pragma("unroll")                                                     \
        for (int _i = 0; _i < 2; ++_i) {                                      \
            int _c = tid + _i * 256;                                          \
            int _r = _c >> 2, _k8 = _c & 3;                                   \
            CP_ASYNC16(_dB + (_r * PADS + _k8 * 8) * 2,                       \
                       B + (size_t)(col0 + _r) * ldb + _kc + _k8 * 8);        \
        }                                                                     \
    } while (0)

    LOAD_STAGE(0, 0);
    LOAD_STAGE(1, 1);
    CP_COMMIT();

    for (int c = 0; c < NC2; ++c) {
        CP_WAIT(0);
        __syncthreads();

        if (c + 1 < NC2) {
            const int pb = ((c + 1) & 1) << 1;
            LOAD_STAGE(pb, 2 * (c + 1));
            LOAD_STAGE(pb + 1, 2 * (c + 1) + 1);
        }
        CP_COMMIT();

        const int cb = (c & 1) << 1;
#pragma unroll
        for (int hs = 0; hs < 2; hs++) {
            const uint32_t baseA = sbase + (cb + hs) * (STAGE_ELEMS * 2);
            const uint32_t baseB = sbase + (NSTAGE + cb + hs) * (STAGE_ELEMS * 2);
#pragma unroll
            for (int kk = 0; kk < 32; kk += 16) {
                uint32_t a[2][4];
#pragma unroll
                for (int mt = 0; mt < 2; mt++) {
                    int r = wm * 32 + mt * 16 + (lane & 15);
                    int kc = kk + ((lane & 16) ? 8 : 0);
                    ldmatrix_x4(a[mt][0], a[mt][1], a[mt][2], a[mt][3],
                                baseA + (r * PADS + kc) * 2);
                }
                uint32_t b[8][2];
#pragma unroll
                for (int np = 0; np < 4; np++) {
                    int n = wn * 64 + np * 16 + (lane & 7) + ((lane & 16) ? 8 : 0);
                    int kc = kk + ((lane & 8) ? 8 : 0);
                    ldmatrix_x4(b[2 * np][0], b[2 * np][1], b[2 * np + 1][0], b[2 * np + 1][1],
                                baseB + (n * PADS + kc) * 2);
                }
#pragma unroll
                for (int mt = 0; mt < 2; mt++)
#pragma unroll
                    for (int nt = 0; nt < 8; nt++)
                        mma_f16(acc[mt][nt], a[mt], b[nt]);
            }
        }
    }

    // ---- epilogue ----
    float* outf = Cf;
    __half* outh = Ch;
    int ostride = N, coff = 0;
    int write_half = (mode == 1);
    if (mode == 2) {
        if (col0 < 256)      { outh = Ch;  ostride = 256; coff = 0;   write_half = 1; }
        else if (col0 < 512) { outh = C2h; ostride = 256; coff = 256; write_half = 1; }
        else                 { outf = C3;  ostride = 128; coff = 512; }
    }

#pragma unroll
    for (int mt = 0; mt < 2; mt++) {
#pragma unroll
        for (int half_i = 0; half_i < 2; half_i++) {
            int r = row0 + wm * 32 + mt * 16 + (lane >> 2) + half_i * 8;
            if (r >= M) continue;
#pragma unroll
            for (int nt = 0; nt < 8; nt++) {
                int cidx = col0 + wn * 64 + nt * 8 + (lane & 3) * 2;
                float v0 = acc[mt][nt][half_i * 2 + 0] + bias[cidx];
                float v1 = acc[mt][nt][half_i * 2 + 1] + bias[cidx + 1];
                if (relu) { v0 = fmaxf(v0, 0.f); v1 = fmaxf(v1, 0.f); }
                if (write_half) {
                    __half2 hv;
                    hv.x = __float2half_rn(v0);
                    hv.y = __float2half_rn(v1);
                    *reinterpret_cast<__half2*>(outh + (size_t)r * ostride + (cidx - coff)) = hv;
                } else {
                    float2 o = make_float2(v0, v1);
                    *reinterpret_cast<float2*>(outf + (size_t)r * ostride + (cidx - coff)) = o;
                }
            }
        }
    }
#undef LOAD_STAGE
}

// ---------------- GEMM + residual(fp16) + LayerNorm fused (N = 256) --------
#define A_ST (128 * PADS * 2)
#define B_ST (256 * PADS * 2)
#define GEMMLN_SMEM (NSTAGE * (A_ST + B_ST))   // 122880 bytes

__global__ __launch_bounds__(512, 1)
void gemm_ln(const __half* __restrict__ A, int lda,
             const __half* __restrict__ B,
             const float* __restrict__ bias,
             const __half* __restrict__ resid,
             const float* __restrict__ lng, const float* __restrict__ lnb,
             float* __restrict__ out, __half* __restrict__ outh,
             int M, int K)
{
    extern __shared__ __align__(16) __half dynsmem[];

    const int tid  = threadIdx.x;
    const int wid  = tid >> 5;
    const int lane = tid & 31;
    const int wm   = wid & 3;
    const int wn   = wid >> 2;
    const int row0 = blockIdx.y * 128;

    const uint32_t sbase = smem_u32(dynsmem);
    const uint32_t sbB = sbase + NSTAGE * A_ST;
    const int NC2 = K >> 6;

    float acc[2][8][4];
#pragma unroll
    for (int i = 0; i < 2; i++)
#pragma unroll
        for (int j = 0; j < 8; j++)
#pragma unroll
            for (int t = 0; t < 4; t++) acc[i][j][t] = 0.f;

#define LOAD_STAGE_LN(buf, cc) do {                                           \
        int _kc = (cc) << 5;                                                  \
        uint32_t _dA = sbase + (buf) * A_ST;                                  \
        uint32_t _dB = sbB + (buf) * B_ST;                                    \
        {                                                                     \
            int _r = tid >> 2, _k8 = tid & 3;                                 \
            int _gr = row0 + _r; if (_gr >= M) _gr = M - 1;                   \
            CP_ASYNC16(_dA + (_r * PADS + _k8 * 8) * 2,                       \
                       A + (size_t)_gr * lda + _kc + _k8 * 8);                \
        }                                                                     \
        _Pragma("unroll")                                                     \
        for (int _i = 0; _i < 2; ++_i) {                                      \
            int _c = tid + _i * 512;                                          \
            int _r = _c >> 2, _k8 = _c & 3;                                   \
            CP_ASYNC16(_dB + (_r * PADS + _k8 * 8) * 2,                       \
                       B + (size_t)_r * K + _kc + _k8 * 8);                   \
        }                                                                     \
    } while (0)

    LOAD_STAGE_LN(0, 0);
    LOAD_STAGE_LN(1, 1);
    CP_COMMIT();

    for (int c = 0; c < NC2; ++c) {
        CP_WAIT(0);
        __syncthreads();

        if (c + 1 < NC2) {
            const int pb = ((c + 1) & 1) << 1;
            LOAD_STAGE_LN(pb, 2 * (c + 1));
            LOAD_STAGE_LN(pb + 1, 2 * (c + 1) + 1);
        }
        CP_COMMIT();

        const int cb = (c & 1) << 1;
#pragma unroll
        for (int hs = 0; hs < 2; hs++) {
            const uint32_t baseA = sbase + (cb + hs) * A_ST;
            const uint32_t baseB = sbB + (cb + hs) * B_ST;
#pragma unroll
            for (int kk = 0; kk < 32; kk += 16) {
                uint32_t a[2][4];
#pragma unroll
                for (int mt = 0; mt < 2; mt++) {
                    int r = wm * 32 + mt * 16 + (lane & 15);
                    int kc = kk + ((lane & 16) ? 8 : 0);
                    ldmatrix_x4(a[mt][0], a[mt][1], a[mt][2], a[mt][3],
                                baseA + (r * PADS + kc) * 2);
                }
                uint32_t b[8][2];
#pragma unroll
                for (int np = 0; np < 4; np++) {
                    int n = wn * 64 + np * 16 + (lane & 7) + ((lane & 16) ? 8 : 0);
                    int kc = kk + ((lane & 8) ? 8 : 0);
                    ldmatrix_x4(b[2 * np][0], b[2 * np][1], b[2 * np + 1][0], b[2 * np + 1][1],
                                baseB + (n * PADS + kc) * 2);
                }
#pragma unroll
                for (int mt = 0; mt < 2; mt++)
#pragma unroll
                    for (int nt = 0; nt < 8; nt++)
                        mma_f16(acc[mt][nt], a[mt], b[nt]);
            }
        }
    }

    // ---- fused epilogue: bias + fp16 residual + per-row LayerNorm ----
    __syncthreads();
    float* red = reinterpret_cast<float*>(dynsmem);

#pragma unroll
    for (int mt = 0; mt < 2; mt++) {
#pragma unroll
        for (int hf = 0; hf < 2; hf++) {
            int lr = wm * 32 + mt * 16 + (lane >> 2) + hf * 8;
            int r = row0 + lr;
            int rc = (r < M) ? r : (M - 1);
            float s1 = 0.f, s2 = 0.f;
#pragma unroll
            for (int nt = 0; nt < 8; nt++) {
                int cidx = wn * 64 + nt * 8 + (lane & 3) * 2;
                __half2 rh = *reinterpret_cast<const __half2*>(resid + (size_t)rc * 256 + cidx);
                float2 res = __half22float2(rh);
                float2 bv = *reinterpret_cast<const float2*>(bias + cidx);
                float v0 = acc[mt][nt][hf * 2 + 0] + bv.x + res.x;
                float v1 = acc[mt][nt][hf * 2 + 1] + bv.y + res.y;
                acc[mt][nt][hf * 2 + 0] = v0;
                acc[mt][nt][hf * 2 + 1] = v1;
                s1 += v0 + v1;
                s2 += v0 * v0 + v1 * v1;
            }
            s1 += __shfl_xor_sync(0xffffffffu, s1, 1);
            s2 += __shfl_xor_sync(0xffffffffu, s2, 1);
            s1 += __shfl_xor_sync(0xffffffffu, s1, 2);
            s2 += __shfl_xor_sync(0xffffffffu, s2, 2);
            if ((lane & 3) == 0) {
                red[(wn * 128 + lr) * 2 + 0] = s1;
                red[(wn * 128 + lr) * 2 + 1] = s2;
            }
        }
    }
    __syncthreads();

#pragma unroll
    for (int mt = 0; mt < 2; mt++) {
#pragma unroll
        for (int hf = 0; hf < 2; hf++) {
            int lr = wm * 32 + mt * 16 + (lane >> 2) + hf * 8;
            int r = row0 + lr;
            if (r >= M) continue;
            float t1 = red[(0 * 128 + lr) * 2 + 0] + red[(1 * 128 + lr) * 2 + 0]
                     + red[(2 * 128 + lr) * 2 + 0] + red[(3 * 128 + lr) * 2 + 0];
            float t2 = red[(0 * 128 + lr) * 2 + 1] + red[(1 * 128 + lr) * 2 + 1]
                     + red[(2 * 128 + lr) * 2 + 1] + red[(3 * 128 + lr) * 2 + 1];
            float mean = t1 * (1.f / 256.f);
            float var = t2 * (1.f / 256.f) - mean * mean;
            float inv = rsqrtf(var + 1e-5f);
#pragma unroll
            for (int nt = 0; nt < 8; nt++) {
                int cidx = wn * 64 + nt * 8 + (lane & 3) * 2;
                float2 gv = *reinterpret_cast<const float2*>(lng + cidx);
                float2 bv = *reinterpret_cast<const float2*>(lnb + cidx);
                float o0 = (acc[mt][nt][hf * 2 + 0] - mean) * inv * gv.x + bv.x;
                float o1 = (acc[mt][nt][hf * 2 + 1] - mean) * inv * gv.y + bv.y;
                if (out)
                    *reinterpret_cast<float2*>(out + (size_t)r * 256 + cidx) = make_float2(o0, o1);
                if (outh) {
                    __half2 hv;
                    hv.x = __float2half_rn(o0);
                    hv.y = __float2half_rn(o1);
                    *reinterpret_cast<__half2*>(outh + (size_t)r * 256 + cidx) = hv;
                }
            }
        }
    }
#undef LOAD_STAGE_LN
}

// ---------------- fused weight prep + qh = fp16(src + pos) -----------------
__device__ __forceinline__ void wtr1(const float* __restrict__ W, __half* __restrict__ Wt,
                                     int K_, int N_, int i)
{
    int k = i / N_, n = i % N_;
    Wt[(size_t)n * K_ + k] = __float2half_rn(W[i]);
}

#define PREP_ITEMS 754304
#define ADD_ITEMS  (MTOK * DMODEL / 4)
#define PA_TOTAL   (PREP_ITEMS + ADD_ITEMS)

__global__ void prep_add_kernel(const float* __restrict__ vW, const float* __restrict__ oW,
                                const float* __restrict__ aW, const float* __restrict__ uW,
                                const float* __restrict__ f1W, const float* __restrict__ f2W,
                                const float* __restrict__ vb, const float* __restrict__ ob,
                                const float* __restrict__ ab,
                                __half* __restrict__ wtp, __half* __restrict__ wtu,
                                __half* __restrict__ wtf1, __half* __restrict__ wtf2,
                                float* __restrict__ biasp,
                                const float* __restrict__ srca, const float* __restrict__ posb,
                                __half* __restrict__ qh)
{
    int i = blockIdx.x * blockDim.x + threadIdx.x;
    if (i >= PREP_ITEMS) {
        int t = i - PREP_ITEMS;
        if (t >= ADD_ITEMS) return;
        float4 x = reinterpret_cast<const float4*>(srca)[t];
        float4 y = reinterpret_cast<const float4*>(posb)[t];
        x.x += y.x; x.y += y.y; x.z += y.z; x.w += y.w;
        __half2 h0 = __floats2half2_rn(x.x, x.y);
        __half2 h1 = __floats2half2_rn(x.z, x.w);
        uint2 hp;
        hp.x = *reinterpret_cast<uint32_t*>(&h0);
        hp.y = *reinterpret_cast<uint32_t*>(&h1);
        reinterpret_cast<uint2*>(qh)[t] = hp;
        return;
    }
    if (i < 65536)       { wtr1(vW, wtp, 256, 256, i); return; }
    i -= 65536;
    if (i < 65536)       { wtr1(oW, wtp + 256 * 256, 256, 256, i); return; }
    i -= 65536;
    if (i < 32768)       { wtr1(aW, wtp + 512 * 256, 256, 128, i); return; }
    i -= 32768;
    if (i < 65536)       { wtr1(uW, wtu, 256, 256, i); return; }
    i -= 65536;
    if (i < 262144)      { wtr1(f1W, wtf1, 256, 1024, i); return; }
    i -= 262144;
    if (i < 262144)      { wtr1(f2W, wtf2, 1024, 256, i); return; }
    i -= 262144;
    if (i < 256)         { biasp[i] = vb[i]; return; }
    if (i < 512)         { biasp[i] = ob[i - 256]; return; }
    if (i < 640)         { biasp[i] = ab[i - 512]; return; }
}

// ---------------- MSDA: fused softmax + float4 gathers (row-major value) ---
__global__ __launch_bounds__(256)
void msda_kernel(const __half* __restrict__ value, const __half* __restrict__ offs,
                 const float* __restrict__ aw, const float* __restrict__ ref,
                 const int* __restrict__ shapes, const int* __restrict__ starts,
                 __half* __restrict__ outh)
{
    const int tok = blockIdx.x;
    const int h = threadIdx.x >> 5;
    const int lane = threadIdx.x & 31;
    const int j = lane & 15;
    const int b = tok / LIN;
    const int l = j >> 2;

    const int Hl = shapes[l * 2 + 0];
    const int Wl = shapes[l * 2 + 1];
    const int st = starts[l];
    const float fW = (float)Wl, fH = (float)Hl;
    const float rx = ref[(size_t)tok * 8 + l * 2 + 0];
    const float ry = ref[(size_t)tok * 8 + l * 2 + 1];
    __half2 offh = *reinterpret_cast<const __half2*>(offs + (size_t)tok * 256 + h * 32 + 2 * j);
    float2 off = __half22float2(offh);

    float logit = aw[(size_t)tok * 128 + h * 16 + j];
    float m = logit;
#pragma unroll
    for (int o = 8; o; o >>= 1) m = fmaxf(m, __shfl_xor_sync(0xffffffffu, m, o, 16));
    float e = expf(logit - m);
    float s = e;
#pragma unroll
    for (int o = 8; o; o >>= 1) s += __shfl_xor_sync(0xffffffffu, s, o, 16);
    float wgt = e / s;

    float x = (rx + off.x / fW) * fW - 0.5f;
    float y = (ry + off.y / fH) * fH - 0.5f;
    float x0f = floorf(x), y0f = floorf(y);
    float dx = x - x0f, dy = y - y0f;
    int x0 = (int)x0f, y0 = (int)y0f;
    int x1 = x0 + 1, y1 = y0 + 1;

    bool xv0 = (x0 >= 0) & (x0 < Wl);
    bool xv1 = (x1 >= 0) & (x1 < Wl);
    bool yv0 = (y0 >= 0) & (y0 < Hl);
    bool yv1 = (y1 >= 0) & (y1 < Hl);

    float w00 = (xv0 && yv0) ? wgt * (1.f - dx) * (1.f - dy) : 0.f;
    float w10 = (xv1 && yv0) ? wgt * dx * (1.f - dy) : 0.f;
    float w01 = (xv0 && yv1) ? wgt * (1.f - dx) * dy : 0.f;
    float w11 = (xv1 && yv1) ? wgt * dx * dy : 0.f;

    int cx0 = min(max(x0, 0), Wl - 1), cx1 = min(max(x1, 0), Wl - 1);
    int cy0 = min(max(y0, 0), Hl - 1), cy1 = min(max(y1, 0), Hl - 1);
    const int base = b * LIN + st;
    int i00 = base + cy0 * Wl + cx0;
    int i10 = base + cy0 * Wl + cx1;
    int i01 = base + cy1 * Wl + cx0;
    int i11 = base + cy1 * Wl + cx1;

    const int g = lane >> 2;
    const int c4 = lane & 3;
    const __half* vch = value + h * DH + c4 * 8;
    float acc[8] = {0.f, 0.f, 0.f, 0.f, 0.f, 0.f, 0.f, 0.f};

#pragma unroll
    for (int p = 0; p < 2; p++) {
        const int pt = p * 8 + g;
        int a00 = __shfl_sync(0xffffffffu, i00, pt);
        int a10 = __shfl_sync(0xffffffffu, i10, pt);
        int a01 = __shfl_sync(0xffffffffu, i01, pt);
        int a11 = __shfl_sync(0xffffffffu, i11, pt);
        float u00 = __shfl_sync(0xffffffffu, w00, pt);
        float u10 = __shfl_sync(0xffffffffu, w10, pt);
        float u01 = __shfl_sync(0xffffffffu, w01, pt);
        float u11 = __shfl_sync(0xffffffffu, w11, pt);

        uint4 r00 = *reinterpret_cast<const uint4*>(vch + (size_t)a00 * DMODEL);
        uint4 r10 = *reinterpret_cast<const uint4*>(vch + (size_t)a10 * DMODEL);
        uint4 r01 = *reinterpret_cast<const uint4*>(vch + (size_t)a01 * DMODEL);
        uint4 r11 = *reinterpret_cast<const uint4*>(vch + (size_t)a11 * DMODEL);

#define ACC8(rv, u) do {                                                      \
        const __half2* _h = reinterpret_cast<const __half2*>(&(rv));          \
        _Pragma("unroll")                                                     \
        for (int _k = 0; _k < 4; _k++) {                                      \
            float2 _f = __half22float2(_h[_k]);                               \
            acc[2 * _k + 0] = fmaf(u, _f.x, acc[2 * _k + 0]);                 \
            acc[2 * _k + 1] = fmaf(u, _f.y, acc[2 * _k + 1]);                 \
        } } while (0)

        ACC8(r00, u00);
        ACC8(r10, u10);
        ACC8(r01, u01);
        ACC8(r11, u11);
#undef ACC8
    }

#pragma unroll
    for (int o = 4; o <= 16; o <<= 1) {
#pragma unroll
        for (int k = 0; k < 8; k++)
            acc[k] += __shfl_xor_sync(0xffffffffu, acc[k], o);
    }

    if (lane < 4) {
        __half2 h0 = __floats2half2_rn(acc[0], acc[1]);
        __half2 h1 = __floats2half2_rn(acc[2], acc[3]);
        __half2 h2 = __floats2half2_rn(acc[4], acc[5]);
        __half2 h3 = __floats2half2_rn(acc[6], acc[7]);
        uint4 o;
        o.x = *reinterpret_cast<uint32_t*>(&h0);
        o.y = *reinterpret_cast<uint32_t*>(&h1);
        o.z = *reinterpret_cast<uint32_t*>(&h2);
        o.w = *reinterpret_cast<uint32_t*>(&h3);
        *reinterpret_cast<uint4*>(outh + (size_t)tok * DMODEL + h * DH + lane * 8) = o;
    }
}

// ---------------- launch ----------------
extern "C" void kernel_launch(void* const* d_in, const int* in_sizes, int n_in,
                              void* d_out, int out_size)
{
    const float* src    = (const float*)d_in[0];
    const float* pos    = (const float*)d_in[1];
    const float* refpts = (const float*)d_in[2];
    const int*   shapes = (const int*)  d_in[3];
    const int*   starts = (const int*)  d_in[4];
    const float* value_w = (const float*)d_in[5];
    const float* value_b = (const float*)d_in[6];
    const float* offs_w  = (const float*)d_in[7];
    const float* offs_b  = (const float*)d_in[8];
    const float* attn_w  = (const float*)d_in[9];
    const float* attn_b  = (const float*)d_in[10];
    const float* out_w   = (const float*)d_in[11];
    const float* out_b   = (const float*)d_in[12];
    const float* ln1_g   = (const float*)d_in[13];
    const float* ln1_b   = (const float*)d_in[14];
    const float* ff1_w   = (const float*)d_in[15];
    const float* ff1_b   = (const float*)d_in[16];
    const float* ff2_w   = (const float*)d_in[17];
    const float* ff2_b   = (const float*)d_in[18];
    const float* ln2_g   = (const float*)d_in[19];
    const float* ln2_b   = (const float*)d_in[20];
    float* outp = (float*)d_out;

    float *aw, *biasp;
    __half *qh, *value, *offs, *msdah, *xh, *ffh;
    __half *wtp, *wtu, *wtf1, *wtf2;
    cudaGetSymbolAddress((void**)&qh,    g_qh);
    cudaGetSymbolAddress((void**)&value, g_value);
    cudaGetSymbolAddress((void**)&offs,  g_offs);
    cudaGetSymbolAddress((void**)&aw,    g_aw);
    cudaGetSymbolAddress((void**)&msdah, g_msdah);
    cudaGetSymbolAddress((void**)&xh,    g_xh);
    cudaGetSymbolAddress((void**)&ffh,   g_ffh);
    cudaGetSymbolAddress((void**)&wtp,   g_wt_proj);
    cudaGetSymbolAddress((void**)&wtu,   g_wt_out);
    cudaGetSymbolAddress((void**)&wtf1,  g_wt_ff1);
    cudaGetSymbolAddress((void**)&wtf2,  g_wt_ff2);
    cudaGetSymbolAddress((void**)&biasp, g_bias_proj);

    cudaFuncSetAttribute(gemm_mma, cudaFuncAttributeMaxDynamicSharedMemorySize, GEMM_SMEM);
    cudaFuncSetAttribute(gemm_ln, cudaFuncAttributeMaxDynamicSharedMemorySize, GEMMLN_SMEM);

    const int M = MTOK;
    const int gy = (M + 127) / 128;

    // 0. fused weight prep + qh = fp16(src + pos)
    prep_add_kernel<<<(PA_TOTAL + 255) / 256, 256>>>(value_w, offs_w, attn_w, out_w, ff1_w, ff2_w,
                                                     value_b, offs_b, attn_b,
                                                     wtp, wtu, wtf1, wtf2, biasp,
                                                     src, pos, qh);

    // 1. fused projections: [value(fp16) | offs(fp16) | aw(fp32)] = qh @ Wp^T
    gemm_mma<<<dim3(5, gy), 256, GEMM_SMEM>>>(qh, 256, wtp, 256, biasp,
                                              nullptr, value, offs, aw, M, 256, 640, 0, 2);

    // 2. deformable sampling with fused softmax
    msda_kernel<<<M, 256>>>(value, offs, aw, refpts, shapes, starts, msdah);

    // 3. xh = fp16(LN(qh + msda @ out_w + out_b))   [fused GEMM+LN]
    gemm_ln<<<dim3(1, gy), 512, GEMMLN_SMEM>>>(msdah, 256, wtu, out_b,
                                               qh, ln1_g, ln1_b, nullptr, xh, M, 256);

    // 4. ffh = relu(xh @ ff1_w + ff1_b) -> fp16
    gemm_mma<<<dim3(8, gy), 256, GEMM_SMEM>>>(xh, 256, wtf1, 256, ff1_b,
                                              nullptr, ffh, nullptr, nullptr, M, 256, 1024, 1, 1);

    // 5. out = LN(xh + ffh @ ff2_w + ff2_b)   [fused GEMM+LN]
    gemm_ln<<<dim3(1, gy), 512, GEMMLN_SMEM>>>(ffh, 1024, wtf2, ff2_b,
                                               xh, ln2_g, ln2_b, outp, nullptr, M, 1024);
}

// round 16
// speedup vs baseline: 1.0889x; 1.0291x over previous
#include <cuda_runtime.h>
#include <cuda_fp16.h>
#include <cstdint>
#include <math.h>

// ---------------- problem constants ----------------
#define Bq    4
#define LIN   13294
#define MTOK  (Bq * LIN)      // 53176
#define DMODEL 256
#define NHEAD 8
#define NLVL  4
#define NPTS  4
#define DH    32
#define DFF   1024

// ---------------- scratch (device globals) ----------------
__device__ __half g_qh   [(size_t)MTOK * DMODEL];
__device__ __half g_value[(size_t)MTOK * DMODEL];   // TRANSPOSED: [head][MTOK][32]
__device__ __half g_offs [(size_t)MTOK * DMODEL];   // fp16
__device__ float  g_aw   [(size_t)MTOK * 128];      // raw logits (fp32)
__device__ __half g_msdah[(size_t)MTOK * DMODEL];
__device__ __half g_xh   [(size_t)MTOK * DMODEL];
__device__ __half g_ffh  [(size_t)MTOK * DFF];
// weights: Wt[N, K] fp16 K-major
__device__ __half g_wt_proj[640 * 256];
__device__ __half g_wt_out [256 * 256];
__device__ __half g_wt_ff1 [1024 * 256];
__device__ __half g_wt_ff2 [256 * 1024];
__device__ float  g_bias_proj[640];

// ---------------- helpers ----------------
__device__ __forceinline__ uint32_t smem_u32(const void* p) {
    uint32_t a;
    asm("{ .reg .u64 t; cvta.to.shared.u64 t, %1; cvt.u32.u64 %0, t; }" : "=r"(a) : "l"(p));
    return a;
}
#define CP_ASYNC16(dst, src) \
    asm volatile("cp.async.cg.shared.global [%0], [%1], 16;\n" :: "r"(dst), "l"(src) : "memory")
#define CP_COMMIT() asm volatile("cp.async.commit_group;\n" ::: "memory")
#define CP_WAIT(n)  asm volatile("cp.async.wait_group %0;\n" :: "n"(n) : "memory")

__device__ __forceinline__ void ldmatrix_x4(uint32_t& r0, uint32_t& r1, uint32_t& r2, uint32_t& r3, uint32_t addr) {
    asm volatile("ldmatrix.sync.aligned.m8n8.x4.shared.b16 {%0,%1,%2,%3}, [%4];"
                 : "=r"(r0), "=r"(r1), "=r"(r2), "=r"(r3) : "r"(addr));
}
__device__ __forceinline__ void mma_f16(float* c, const uint32_t* a, const uint32_t* b) {
    asm volatile("mma.sync.aligned.m16n8k16.row.col.f32.f16.f16.f32 "
                 "{%0,%1,%2,%3}, {%4,%5,%6,%7}, {%8,%9}, {%0,%1,%2,%3};"
                 : "+f"(c[0]), "+f"(c[1]), "+f"(c[2]), "+f"(c[3])
                 : "r"(a[0]), "r"(a[1]), "r"(a[2]), "r"(a[3]), "r"(b[0]), "r"(b[1]));
}

#define PADS 40
#define STAGE_ELEMS (128 * PADS)
#define NSTAGE 4
#define GEMM_SMEM (2 * NSTAGE * STAGE_ELEMS * 2)   // 81920 bytes

// ---------------- fp16 warp-MMA GEMM (pair-buffered) — proj / ff1 ----------
// 128x128 tile, 8 warps (4 wm x 2 wn, warp tile 32x64).
// mode 1: Ch fp16 [M,N].
// mode 2: cols 0-255 -> Ch fp16, TRANSPOSED value layout [head][MTOK][32],
//         written via smem staging for coalescing;
//         256-511 -> C2h fp16 (offs,256); 512-639 -> C3 fp32 (aw,128).
__global__ __launch_bounds__(256, 2)
void gemm_mma(const __half* __restrict__ A, int lda,
              const __half* __restrict__ B, int ldb,
              const float* __restrict__ bias,
              float* __restrict__ Cf, __half* __restrict__ Ch,
              __half* __restrict__ C2h, float* __restrict__ C3,
              int M, int K, int N, int relu, int mode)
{
    extern __shared__ __align__(16) __half dynsmem[];

    const int tid  = threadIdx.x;
    const int wid  = tid >> 5;
    const int lane = tid & 31;
    const int wm   = wid & 3;
    const int wn   = wid >> 2;
    const int row0 = blockIdx.y * 128;
    const int col0 = blockIdx.x * 128;

    const uint32_t sbase = smem_u32(dynsmem);
    const int NC2 = K >> 6;

    float acc[2][8][4];
#pragma unroll
    for (int i = 0; i < 2; i++)
#pragma unroll
        for (int j = 0; j < 8; j++)
#pragma unroll
            for (int t = 0; t < 4; t++) acc[i][j][t] = 0.f;

#define LOAD_STAGE(buf, cc) do {                                              \
        int _kc = (cc) << 5;                                                  \
        uint32_t _dA = sbase + (buf) * (STAGE_ELEMS * 2);                     \
        uint32_t _dB = sbase + (NSTAGE + (buf)) * (STAGE_ELEMS * 2);          \
        _Pragma("unroll")                                                     \
        for (int _i = 0; _i < 2; ++_i) {                                      \
            int _c = tid + _i * 256;                                          \
            int _r = _c >> 2, _k8 = _c & 3;                                   \
            int _gr = row0 + _r; if (_gr >= M) _gr = M - 1;                   \
            CP_ASYNC16(_dA + (_r * PADS + _k8 * 8) * 2,                       \
                       A + (size_t)_gr * lda + _kc + _k8 * 8);                \
        }                                                                     \
        _Pragma("unroll")                                                     \
        for (int _i = 0; _i < 2; ++_i) {                                      \
            int _c = tid + _i * 256;                                          \
            int _r = _c >> 2, _k8 = _c & 3;                                   \
            CP_ASYNC16(_dB + (_r * PADS + _k8 * 8) * 2,                       \
                       B + (size_t)(col0 + _r) * ldb + _kc + _k8 * 8);        \
        }                                                                     \
    } while (0)

    LOAD_STAGE(0, 0);
    LOAD_STAGE(1, 1);
    CP_COMMIT();

    for (int c = 0; c < NC2; ++c) {
        CP_WAIT(0);
        __syncthreads();

        if (c + 1 < NC2) {
            const int pb = ((c + 1) & 1) << 1;
            LOAD_STAGE(pb, 2 * (c + 1));
            LOAD_STAGE(pb + 1, 2 * (c + 1) + 1);
        }
        CP_COMMIT();

        const int cb = (c & 1) << 1;
#pragma unroll
        for (int hs = 0; hs < 2; hs++) {
            const uint32_t baseA = sbase + (cb + hs) * (STAGE_ELEMS * 2);
            const uint32_t baseB = sbase + (NSTAGE + cb + hs) * (STAGE_ELEMS * 2);
#pragma unroll
            for (int kk = 0; kk < 32; kk += 16) {
                uint32_t a[2][4];
#pragma unroll
                for (int mt = 0; mt < 2; mt++) {
                    int r = wm * 32 + mt * 16 + (lane & 15);
                    int kc = kk + ((lane & 16) ? 8 : 0);
                    ldmatrix_x4(a[mt][0], a[mt][1], a[mt][2], a[mt][3],
                                baseA + (r * PADS + kc) * 2);
                }
                uint32_t b[8][2];
#pragma unroll
                for (int np = 0; np < 4; np++) {
                    int n = wn * 64 + np * 16 + (lane & 7) + ((lane & 16) ? 8 : 0);
                    int kc = kk + ((lane & 8) ? 8 : 0);
                    ldmatrix_x4(b[2 * np][0], b[2 * np][1], b[2 * np + 1][0], b[2 * np + 1][1],
                                baseB + (n * PADS + kc) * 2);
                }
#pragma unroll
                for (int mt = 0; mt < 2; mt++)
#pragma unroll
                    for (int nt = 0; nt < 8; nt++)
                        mma_f16(acc[mt][nt], a[mt], b[nt]);
            }
        }
    }

    // ---- epilogue ----
    if (mode == 2 && col0 < 256) {
        // value region: stage in smem, write TRANSPOSED [head][MTOK][32] coalesced
        __syncthreads();                       // mainloop smem reads done
        __half* so = dynsmem;                  // [128][136] halfs = 34816 B
#pragma unroll
        for (int mt = 0; mt < 2; mt++) {
#pragma unroll
            for (int hf = 0; hf < 2; hf++) {
                int r = wm * 32 + mt * 16 + (lane >> 2) + hf * 8;
#pragma unroll
                for (int nt = 0; nt < 8; nt++) {
                    int cc = wn * 64 + nt * 8 + (lane & 3) * 2;
                    float v0 = acc[mt][nt][hf * 2 + 0] + bias[col0 + cc];
                    float v1 = acc[mt][nt][hf * 2 + 1] + bias[col0 + cc + 1];
                    *reinterpret_cast<__half2*>(so + r * 136 + cc) = __floats2half2_rn(v0, v1);
                }
            }
        }
        __syncthreads();
#pragma unroll
        for (int h4 = 0; h4 < 4; h4++) {
            int head = (col0 >> 5) + h4;
            __half* dst = Ch + ((size_t)head * MTOK + row0) * 32;
#pragma unroll
            for (int it = 0; it < 2; it++) {
                int idx = tid * 2 + it;        // 0..511 (uint4 units of 8 halfs)
                int r = idx >> 2;
                int cu = (idx & 3) * 8;
                if (row0 + r < M) {
                    const __half* sp = so + r * 136 + h4 * 32 + cu;
                    uint4 v;
                    v.x = *reinterpret_cast<const uint32_t*>(sp + 0);
                    v.y = *reinterpret_cast<const uint32_t*>(sp + 2);
                    v.z = *reinterpret_cast<const uint32_t*>(sp + 4);
                    v.w = *reinterpret_cast<const uint32_t*>(sp + 6);
                    *reinterpret_cast<uint4*>(dst + (size_t)r * 32 + cu) = v;
                }
            }
        }
        return;
    }

    float* outf = Cf;
    __half* outh = nullptr;
    int ostride = N, coff = 0;
    int write_half = (mode == 1);
    if (mode == 1) outh = Ch;
    if (mode == 2) {
        if (col0 < 512) { outh = C2h; ostride = 256; coff = 256; write_half = 1; }
        else            { outf = C3;  ostride = 128; coff = 512; }
    }

#pragma unroll
    for (int mt = 0; mt < 2; mt++) {
#pragma unroll
        for (int half_i = 0; half_i < 2; half_i++) {
            int r = row0 + wm * 32 + mt * 16 + (lane >> 2) + half_i * 8;
            if (r >= M) continue;
#pragma unroll
            for (int nt = 0; nt < 8; nt++) {
                int cidx = col0 + wn * 64 + nt * 8 + (lane & 3) * 2;
                float v0 = acc[mt][nt][half_i * 2 + 0] + bias[cidx];
                float v1 = acc[mt][nt][half_i * 2 + 1] + bias[cidx + 1];
                if (relu) { v0 = fmaxf(v0, 0.f); v1 = fmaxf(v1, 0.f); }
                if (write_half) {
                    __half2 hv;
                    hv.x = __float2half_rn(v0);
                    hv.y = __float2half_rn(v1);
                    *reinterpret_cast<__half2*>(outh + (size_t)r * ostride + (cidx - coff)) = hv;
                } else {
                    float2 o = make_float2(v0, v1);
                    *reinterpret_cast<float2*>(outf + (size_t)r * ostride + (cidx - coff)) = o;
                }
            }
        }
    }
#undef LOAD_STAGE
}

// ---------------- GEMM + residual(fp16) + LayerNorm fused (N = 256) --------
#define A_ST (128 * PADS * 2)
#define B_ST (256 * PADS * 2)
#define GEMMLN_SMEM (NSTAGE * (A_ST + B_ST))   // 122880 bytes

__global__ __launch_bounds__(512, 1)
void gemm_ln(const __half* __restrict__ A, int lda,
             const __half* __restrict__ B,
             const float* __restrict__ bias,
             const __half* __restrict__ resid,
             const float* __restrict__ lng, const float* __restrict__ lnb,
             float* __restrict__ out, __half* __restrict__ outh,
             int M, int K)
{
    extern __shared__ __align__(16) __half dynsmem[];

    const int tid  = threadIdx.x;
    const int wid  = tid >> 5;
    const int lane = tid & 31;
    const int wm   = wid & 3;
    const int wn   = wid >> 2;
    const int row0 = blockIdx.y * 128;

    const uint32_t sbase = smem_u32(dynsmem);
    const uint32_t sbB = sbase + NSTAGE * A_ST;
    const int NC2 = K >> 6;

    float acc[2][8][4];
#pragma unroll
    for (int i = 0; i < 2; i++)
#pragma unroll
        for (int j = 0; j < 8; j++)
#pragma unroll
            for (int t = 0; t < 4; t++) acc[i][j][t] = 0.f;

#define LOAD_STAGE_LN(buf, cc) do {                                           \
        int _kc = (cc) << 5;                                                  \
        uint32_t _dA = sbase + (buf) * A_ST;                                  \
        uint32_t _dB = sbB + (buf) * B_ST;                                    \
        {                                                                     \
            int _r = tid >> 2, _k8 = tid & 3;                                 \
            int _gr = row0 + _r; if (_gr >= M) _gr = M - 1;                   \
            CP_ASYNC16(_dA + (_r * PADS + _k8 * 8) * 2,                       \
                       A + (size_t)_gr * lda + _kc + _k8 * 8);                \
        }                                                                     \
        _Pragma("unroll")                                                     \
        for (int _i = 0; _i < 2; ++_i) {                                      \
            int _c = tid + _i * 512;                                          \
            int _r = _c >> 2, _k8 = _c & 3;                                   \
            CP_ASYNC16(_dB + (_r * PADS + _k8 * 8) * 2,                       \
                       B + (size_t)_r * K + _kc + _k8 * 8);                   \
        }                                                                     \
    } while (0)

    LOAD_STAGE_LN(0, 0);
    LOAD_STAGE_LN(1, 1);
    CP_COMMIT();

    for (int c = 0; c < NC2; ++c) {
        CP_WAIT(0);
        __syncthreads();

        if (c + 1 < NC2) {
            const int pb = ((c + 1) & 1) << 1;
            LOAD_STAGE_LN(pb, 2 * (c + 1));
            LOAD_STAGE_LN(pb + 1, 2 * (c + 1) + 1);
        }
        CP_COMMIT();

        const int cb = (c & 1) << 1;
#pragma unroll
        for (int hs = 0; hs < 2; hs++) {
            const uint32_t baseA = sbase + (cb + hs) * A_ST;
            const uint32_t baseB = sbB + (cb + hs) * B_ST;
#pragma unroll
            for (int kk = 0; kk < 32; kk += 16) {
                uint32_t a[2][4];
#pragma unroll
                for (int mt = 0; mt < 2; mt++) {
                    int r = wm * 32 + mt * 16 + (lane & 15);
                    int kc = kk + ((lane & 16) ? 8 : 0);
                    ldmatrix_x4(a[mt][0], a[mt][1], a[mt][2], a[mt][3],
                                baseA + (r * PADS + kc) * 2);
                }
                uint32_t b[8][2];
#pragma unroll
                for (int np = 0; np < 4; np++) {
                    int n = wn * 64 + np * 16 + (lane & 7) + ((lane & 16) ? 8 : 0);
                    int kc = kk + ((lane & 8) ? 8 : 0);
                    ldmatrix_x4(b[2 * np][0], b[2 * np][1], b[2 * np + 1][0], b[2 * np + 1][1],
                                baseB + (n * PADS + kc) * 2);
                }
#pragma unroll
                for (int mt = 0; mt < 2; mt++)
#pragma unroll
                    for (int nt = 0; nt < 8; nt++)
                        mma_f16(acc[mt][nt], a[mt], b[nt]);
            }
        }
    }

    // ---- fused epilogue: bias + fp16 residual + per-row LayerNorm ----
    __syncthreads();
    float* red = reinterpret_cast<float*>(dynsmem);

#pragma unroll
    for (int mt = 0; mt < 2; mt++) {
#pragma unroll
        for (int hf = 0; hf < 2; hf++) {
            int lr = wm * 32 + mt * 16 + (lane >> 2) + hf * 8;
            int r = row0 + lr;
            int rc = (r < M) ? r : (M - 1);
            float s1 = 0.f, s2 = 0.f;
#pragma unroll
            for (int nt = 0; nt < 8; nt++) {
                int cidx = wn * 64 + nt * 8 + (lane & 3) * 2;
                __half2 rh = *reinterpret_cast<const __half2*>(resid + (size_t)rc * 256 + cidx);
                float2 res = __half22float2(rh);
                float2 bv = *reinterpret_cast<const float2*>(bias + cidx);
                float v0 = acc[mt][nt][hf * 2 + 0] + bv.x + res.x;
                float v1 = acc[mt][nt][hf * 2 + 1] + bv.y + res.y;
                acc[mt][nt][hf * 2 + 0] = v0;
                acc[mt][nt][hf * 2 + 1] = v1;
                s1 += v0 + v1;
                s2 += v0 * v0 + v1 * v1;
            }
            s1 += __shfl_xor_sync(0xffffffffu, s1, 1);
            s2 += __shfl_xor_sync(0xffffffffu, s2, 1);
            s1 += __shfl_xor_sync(0xffffffffu, s1, 2);
            s2 += __shfl_xor_sync(0xffffffffu, s2, 2);
            if ((lane & 3) == 0) {
                red[(wn * 128 + lr) * 2 + 0] = s1;
                red[(wn * 128 + lr) * 2 + 1] = s2;
            }
        }
    }
    __syncthreads();

#pragma unroll
    for (int mt = 0; mt < 2; mt++) {
#pragma unroll
        for (int hf = 0; hf < 2; hf++) {
            int lr = wm * 32 + mt * 16 + (lane >> 2) + hf * 8;
            int r = row0 + lr;
            if (r >= M) continue;
            float t1 = red[(0 * 128 + lr) * 2 + 0] + red[(1 * 128 + lr) * 2 + 0]
                     + red[(2 * 128 + lr) * 2 + 0] + red[(3 * 128 + lr) * 2 + 0];
            float t2 = red[(0 * 128 + lr) * 2 + 1] + red[(1 * 128 + lr) * 2 + 1]
                     + red[(2 * 128 + lr) * 2 + 1] + red[(3 * 128 + lr) * 2 + 1];
            float mean = t1 * (1.f / 256.f);
            float var = t2 * (1.f / 256.f) - mean * mean;
            float inv = rsqrtf(var + 1e-5f);
#pragma unroll
            for (int nt = 0; nt < 8; nt++) {
                int cidx = wn * 64 + nt * 8 + (lane & 3) * 2;
                float2 gv = *reinterpret_cast<const float2*>(lng + cidx);
                float2 bv = *reinterpret_cast<const float2*>(lnb + cidx);
                float o0 = (acc[mt][nt][hf * 2 + 0] - mean) * inv * gv.x + bv.x;
                float o1 = (acc[mt][nt][hf * 2 + 1] - mean) * inv * gv.y + bv.y;
                if (out)
                    *reinterpret_cast<float2*>(out + (size_t)r * 256 + cidx) = make_float2(o0, o1);
                if (outh) {
                    __half2 hv;
                    hv.x = __float2half_rn(o0);
                    hv.y = __float2half_rn(o1);
                    *reinterpret_cast<__half2*>(outh + (size_t)r * 256 + cidx) = hv;
                }
            }
        }
    }
#undef LOAD_STAGE_LN
}

// ---------------- fused weight prep + qh = fp16(src + pos) -----------------
__device__ __forceinline__ void wtr1(const float* __restrict__ W, __half* __restrict__ Wt,
                                     int K_, int N_, int i)
{
    int k = i / N_, n = i % N_;
    Wt[(size_t)n * K_ + k] = __float2half_rn(W[i]);
}

#define PREP_ITEMS 754304
#define ADD_ITEMS  (MTOK * DMODEL / 4)
#define PA_TOTAL   (PREP_ITEMS + ADD_ITEMS)

__global__ void prep_add_kernel(const float* __restrict__ vW, const float* __restrict__ oW,
                                const float* __restrict__ aW, const float* __restrict__ uW,
                                const float* __restrict__ f1W, const float* __restrict__ f2W,
                                const float* __restrict__ vb, const float* __restrict__ ob,
                                const float* __restrict__ ab,
                                __half* __restrict__ wtp, __half* __restrict__ wtu,
                                __half* __restrict__ wtf1, __half* __restrict__ wtf2,
                                float* __restrict__ biasp,
                                const float* __restrict__ srca, const float* __restrict__ posb,
                                __half* __restrict__ qh)
{
    int i = blockIdx.x * blockDim.x + threadIdx.x;
    if (i >= PREP_ITEMS) {
        int t = i - PREP_ITEMS;
        if (t >= ADD_ITEMS) return;
        float4 x = reinterpret_cast<const float4*>(srca)[t];
        float4 y = reinterpret_cast<const float4*>(posb)[t];
        x.x += y.x; x.y += y.y; x.z += y.z; x.w += y.w;
        __half2 h0 = __floats2half2_rn(x.x, x.y);
        __half2 h1 = __floats2half2_rn(x.z, x.w);
        uint2 hp;
        hp.x = *reinterpret_cast<uint32_t*>(&h0);
        hp.y = *reinterpret_cast<uint32_t*>(&h1);
        reinterpret_cast<uint2*>(qh)[t] = hp;
        return;
    }
    if (i < 65536)       { wtr1(vW, wtp, 256, 256, i); return; }
    i -= 65536;
    if (i < 65536)       { wtr1(oW, wtp + 256 * 256, 256, 256, i); return; }
    i -= 65536;
    if (i < 32768)       { wtr1(aW, wtp + 512 * 256, 256, 128, i); return; }
    i -= 32768;
    if (i < 65536)       { wtr1(uW, wtu, 256, 256, i); return; }
    i -= 65536;
    if (i < 262144)      { wtr1(f1W, wtf1, 256, 1024, i); return; }
    i -= 262144;
    if (i < 262144)      { wtr1(f2W, wtf2, 1024, 256, i); return; }
    i -= 262144;
    if (i < 256)         { biasp[i] = vb[i]; return; }
    if (i < 512)         { biasp[i] = ob[i - 256]; return; }
    if (i < 640)         { biasp[i] = ab[i - 512]; return; }
}

// ---------------- MSDA v4: paired-corner coalesced gathers -----------------
// value layout: [head][MTOK][32 ch] (64B per token-head). The two x-corners of
// a point are 64B-adjacent -> 8 lanes (2 corner-sel x 4 chan-quads) load both
// corners of a y-row in ONE 128B-coalesced uint4 access.
__global__ __launch_bounds__(256)
void msda_kernel(const __half* __restrict__ value, const __half* __restrict__ offs,
                 const float* __restrict__ aw, const float* __restrict__ ref,
                 const int* __restrict__ shapes, const int* __restrict__ starts,
                 __half* __restrict__ outh)
{
    const int tok = blockIdx.x;
    const int h = threadIdx.x >> 5;
    const int lane = threadIdx.x & 31;
    const int j = lane & 15;
    const int hi = lane >> 4;
    const int b = tok / LIN;
    const int l = j >> 2;

    // ---- per-point precompute ----
    const int Hl = shapes[l * 2 + 0];
    const int Wl = shapes[l * 2 + 1];
    const int st = starts[l];
    const float fW = (float)Wl, fH = (float)Hl;
    const float rx = ref[(size_t)tok * 8 + l * 2 + 0];
    const float ry = ref[(size_t)tok * 8 + l * 2 + 1];
    __half2 offh = *reinterpret_cast<const __half2*>(offs + (size_t)tok * 256 + h * 32 + 2 * j);
    float2 off = __half22float2(offh);

    float logit = aw[(size_t)tok * 128 + h * 16 + j];
    float m = logit;
#pragma unroll
    for (int o = 8; o; o >>= 1) m = fmaxf(m, __shfl_xor_sync(0xffffffffu, m, o, 16));
    float e = expf(logit - m);
    float s = e;
#pragma unroll
    for (int o = 8; o; o >>= 1) s += __shfl_xor_sync(0xffffffffu, s, o, 16);
    float wgt = e / s;

    float x = (rx + off.x / fW) * fW - 0.5f;
    float y = (ry + off.y / fH) * fH - 0.5f;
    float x0f = floorf(x), y0f = floorf(y);
    float dx = x - x0f, dy = y - y0f;
    int x0 = (int)x0f, y0 = (int)y0f;
    int x1 = x0 + 1, y1 = y0 + 1;

    bool xv0 = (x0 >= 0) & (x0 < Wl);
    bool xv1 = (x1 >= 0) & (x1 < Wl);
    bool yv0 = (y0 >= 0) & (y0 < Hl);
    bool yv1 = (y1 >= 0) & (y1 < Hl);

    float w00 = (xv0 && yv0) ? wgt * (1.f - dx) * (1.f - dy) : 0.f;
    float w10 = (xv1 && yv0) ? wgt * dx * (1.f - dy) : 0.f;
    float w01 = (xv0 && yv1) ? wgt * (1.f - dx) * dy : 0.f;
    float w11 = (xv1 && yv1) ? wgt * dx * dy : 0.f;

    int cx0 = min(max(x0, 0), Wl - 1), cx1 = min(max(x1, 0), Wl - 1);
    int cy0 = min(max(y0, 0), Hl - 1), cy1 = min(max(y1, 0), Hl - 1);
    const int base = b * LIN + st;
    // hi half holds the x1-corner variant
    int ixy0 = base + cy0 * Wl + (hi ? cx1 : cx0);
    int ixy1 = base + cy1 * Wl + (hi ? cx1 : cx0);
    float uwy0 = hi ? w10 : w00;
    float uwy1 = hi ? w11 : w01;

    // ---- gather: 4 passes x 4 points; 8 lanes cover one point (2 corners) --
    const int pg  = lane >> 3;        // point within pass (0..3)
    const int sel = (lane >> 2) & 1;  // x-corner select
    const int c4  = lane & 3;         // channel quad
    const __half* vch = value + (size_t)h * MTOK * 32 + c4 * 8;
    float acc[8] = {0.f, 0.f, 0.f, 0.f, 0.f, 0.f, 0.f, 0.f};

#pragma unroll
    for (int p = 0; p < 4; p++) {
        const int pt = p * 4 + pg;
        const int srcl = pt + (sel << 4);
        int ay = __shfl_sync(0xffffffffu, ixy0, srcl);
        int by = __shfl_sync(0xffffffffu, ixy1, srcl);
        float uy = __shfl_sync(0xffffffffu, uwy0, srcl);
        float vy = __shfl_sync(0xffffffffu, uwy1, srcl);

        uint4 r0 = *reinterpret_cast<const uint4*>(vch + (size_t)ay * 32);
        uint4 r1 = *reinterpret_cast<const uint4*>(vch + (size_t)by * 32);

#define ACC8(rv, u) do {                                                      \
        const __half2* _h = reinterpret_cast<const __half2*>(&(rv));          \
        _Pragma("unroll")                                                     \
        for (int _k = 0; _k < 4; _k++) {                                      \
            float2 _f = __half22float2(_h[_k]);                               \
            acc[2 * _k + 0] = fmaf(u, _f.x, acc[2 * _k + 0]);                 \
            acc[2 * _k + 1] = fmaf(u, _f.y, acc[2 * _k + 1]);                 \
        } } while (0)

        ACC8(r0, uy);
        ACC8(r1, vy);
#undef ACC8
    }

    // ---- reduce over x-corner (xor 4) and point groups (xor 8, 16) ----
#pragma unroll
    for (int o = 4; o <= 16; o <<= 1) {
#pragma unroll
        for (int k = 0; k < 8; k++)
            acc[k] += __shfl_xor_sync(0xffffffffu, acc[k], o);
    }

    if (lane < 4) {
        __half2 h0 = __floats2half2_rn(acc[0], acc[1]);
        __half2 h1 = __floats2half2_rn(acc[2], acc[3]);
        __half2 h2 = __floats2half2_rn(acc[4], acc[5]);
        __half2 h3 = __floats2half2_rn(acc[6], acc[7]);
        uint4 o;
        o.x = *reinterpret_cast<uint32_t*>(&h0);
        o.y = *reinterpret_cast<uint32_t*>(&h1);
        o.z = *reinterpret_cast<uint32_t*>(&h2);
        o.w = *reinterpret_cast<uint32_t*>(&h3);
        *reinterpret_cast<uint4*>(outh + (size_t)tok * DMODEL + h * DH + lane * 8) = o;
    }
}

// ---------------- launch ----------------
extern "C" void kernel_launch(void* const* d_in, const int* in_sizes, int n_in,
                              void* d_out, int out_size)
{
    const float* src    = (const float*)d_in[0];
    const float* pos    = (const float*)d_in[1];
    const float* refpts = (const float*)d_in[2];
    const int*   shapes = (const int*)  d_in[3];
    const int*   starts = (const int*)  d_in[4];
    const float* value_w = (const float*)d_in[5];
    const float* value_b = (const float*)d_in[6];
    const float* offs_w  = (const float*)d_in[7];
    const float* offs_b  = (const float*)d_in[8];
    const float* attn_w  = (const float*)d_in[9];
    const float* attn_b  = (const float*)d_in[10];
    const float* out_w   = (const float*)d_in[11];
    const float* out_b   = (const float*)d_in[12];
    const float* ln1_g   = (const float*)d_in[13];
    const float* ln1_b   = (const float*)d_in[14];
    const float* ff1_w   = (const float*)d_in[15];
    const float* ff1_b   = (const float*)d_in[16];
    const float* ff2_w   = (const float*)d_in[17];
    const float* ff2_b   = (const float*)d_in[18];
    const float* ln2_g   = (const float*)d_in[19];
    const float* ln2_b   = (const float*)d_in[20];
    float* outp = (float*)d_out;

    float *aw, *biasp;
    __half *qh, *value, *offs, *msdah, *xh, *ffh;
    __half *wtp, *wtu, *wtf1, *wtf2;
    cudaGetSymbolAddress((void**)&qh,    g_qh);
    cudaGetSymbolAddress((void**)&value, g_value);
    cudaGetSymbolAddress((void**)&offs,  g_offs);
    cudaGetSymbolAddress((void**)&aw,    g_aw);
    cudaGetSymbolAddress((void**)&msdah, g_msdah);
    cudaGetSymbolAddress((void**)&xh,    g_xh);
    cudaGetSymbolAddress((void**)&ffh,   g_ffh);
    cudaGetSymbolAddress((void**)&wtp,   g_wt_proj);
    cudaGetSymbolAddress((void**)&wtu,   g_wt_out);
    cudaGetSymbolAddress((void**)&wtf1,  g_wt_ff1);
    cudaGetSymbolAddress((void**)&wtf2,  g_wt_ff2);
    cudaGetSymbolAddress((void**)&biasp, g_bias_proj);

    cudaFuncSetAttribute(gemm_mma, cudaFuncAttributeMaxDynamicSharedMemorySize, GEMM_SMEM);
    cudaFuncSetAttribute(gemm_ln, cudaFuncAttributeMaxDynamicSharedMemorySize, GEMMLN_SMEM);

    const int M = MTOK;
    const int gy = (M + 127) / 128;

    // 0. fused weight prep + qh = fp16(src + pos)
    prep_add_kernel<<<(PA_TOTAL + 255) / 256, 256>>>(value_w, offs_w, attn_w, out_w, ff1_w, ff2_w,
                                                     value_b, offs_b, attn_b,
                                                     wtp, wtu, wtf1, wtf2, biasp,
                                                     src, pos, qh);

    // 1. fused projections: [value(fp16, transposed) | offs(fp16) | aw(fp32)]
    gemm_mma<<<dim3(5, gy), 256, GEMM_SMEM>>>(qh, 256, wtp, 256, biasp,
                                              nullptr, value, offs, aw, M, 256, 640, 0, 2);

    // 2. deformable sampling with fused softmax (paired-corner gathers)
    msda_kernel<<<M, 256>>>(value, offs, aw, refpts, shapes, starts, msdah);

    // 3. xh = fp16(LN(qh + msda @ out_w + out_b))   [fused GEMM+LN]
    gemm_ln<<<dim3(1, gy), 512, GEMMLN_SMEM>>>(msdah, 256, wtu, out_b,
                                               qh, ln1_g, ln1_b, nullptr, xh, M, 256);

    // 4. ffh = relu(xh @ ff1_w + ff1_b) -> fp16
    gemm_mma<<<dim3(8, gy), 256, GEMM_SMEM>>>(xh, 256, wtf1, 256, ff1_b,
                                              nullptr, ffh, nullptr, nullptr, M, 256, 1024, 1, 1);

    // 5. out = LN(xh + ffh @ ff2_w + ff2_b)   [fused GEMM+LN]
    gemm_ln<<<dim3(1, gy), 512, GEMMLN_SMEM>>>(ffh, 1024, wtf2, ff2_b,
                                               xh, ln2_g, ln2_b, outp, nullptr, M, 1024);
}

// round 17
// speedup vs baseline: 1.1345x; 1.0418x over previous
#include <cuda_runtime.h>
#include <cuda_fp16.h>
#include <cstdint>
#include <math.h>

// ---------------- problem constants ----------------
#define Bq    4
#define LIN   13294
#define MTOK  (Bq * LIN)      // 53176
#define DMODEL 256
#define NHEAD 8
#define NLVL  4
#define NPTS  4
#define DH    32
#define DFF   1024

// ---------------- scratch (device globals) ----------------
__device__ __half g_qh   [(size_t)MTOK * DMODEL];
__device__ __half g_value[(size_t)MTOK * DMODEL];   // TRANSPOSED: [head][MTOK][32]
__device__ __half g_offs [(size_t)MTOK * DMODEL];   // fp16
__device__ float  g_aw   [(size_t)MTOK * 128];      // raw logits (fp32)
__device__ __half g_msdah[(size_t)MTOK * DMODEL];
__device__ __half g_xh   [(size_t)MTOK * DMODEL];
// weights: Wt[N, K] fp16 K-major
__device__ __half g_wt_proj[640 * 256];
__device__ __half g_wt_out [256 * 256];
__device__ __half g_wt_ff1 [1024 * 256];
__device__ __half g_wt_ff2 [256 * 1024];
__device__ float  g_bias_proj[640];

// ---------------- helpers ----------------
__device__ __forceinline__ uint32_t smem_u32(const void* p) {
    uint32_t a;
    asm("{ .reg .u64 t; cvta.to.shared.u64 t, %1; cvt.u32.u64 %0, t; }" : "=r"(a) : "l"(p));
    return a;
}
#define CP_ASYNC16(dst, src) \
    asm volatile("cp.async.cg.shared.global [%0], [%1], 16;\n" :: "r"(dst), "l"(src) : "memory")
#define CP_COMMIT() asm volatile("cp.async.commit_group;\n" ::: "memory")
#define CP_WAIT(n)  asm volatile("cp.async.wait_group %0;\n" :: "n"(n) : "memory")

__device__ __forceinline__ void ldmatrix_x4(uint32_t& r0, uint32_t& r1, uint32_t& r2, uint32_t& r3, uint32_t addr) {
    asm volatile("ldmatrix.sync.aligned.m8n8.x4.shared.b16 {%0,%1,%2,%3}, [%4];"
                 : "=r"(r0), "=r"(r1), "=r"(r2), "=r"(r3) : "r"(addr));
}
__device__ __forceinline__ void mma_f16(float* c, const uint32_t* a, const uint32_t* b) {
    asm volatile("mma.sync.aligned.m16n8k16.row.col.f32.f16.f16.f32 "
                 "{%0,%1,%2,%3}, {%4,%5,%6,%7}, {%8,%9}, {%0,%1,%2,%3};"
                 : "+f"(c[0]), "+f"(c[1]), "+f"(c[2]), "+f"(c[3])
                 : "r"(a[0]), "r"(a[1]), "r"(a[2]), "r"(a[3]), "r"(b[0]), "r"(b[1]));
}

#define PADS 40
#define STAGE_ELEMS (128 * PADS)
#define NSTAGE 4
#define GEMM_SMEM (2 * NSTAGE * STAGE_ELEMS * 2)   // 81920 bytes

// ---------------- fp16 warp-MMA GEMM (pair-buffered) — projections ---------
// 128x128 tile, 8 warps (4 wm x 2 wn, warp tile 32x64).
// mode 2: cols 0-255 -> Ch fp16, TRANSPOSED value layout [head][MTOK][32]
//         via smem staging; 256-511 -> C2h fp16 (offs,256); 512-639 -> C3 fp32 (aw,128).
__global__ __launch_bounds__(256, 2)
void gemm_mma(const __half* __restrict__ A, int lda,
              const __half* __restrict__ B, int ldb,
              const float* __restrict__ bias,
              float* __restrict__ Cf, __half* __restrict__ Ch,
              __half* __restrict__ C2h, float* __restrict__ C3,
              int M, int K, int N, int relu, int mode)
{
    extern __shared__ __align__(16) __half dynsmem[];

    const int tid  = threadIdx.x;
    const int wid  = tid >> 5;
    const int lane = tid & 31;
    const int wm   = wid & 3;
    const int wn   = wid >> 2;
    const int row0 = blockIdx.y * 128;
    const int col0 = blockIdx.x * 128;

    const uint32_t sbase = smem_u32(dynsmem);
    const int NC2 = K >> 6;

    float acc[2][8][4];
#pragma unroll
    for (int i = 0; i < 2; i++)
#pragma unroll
        for (int j = 0; j < 8; j++)
#pragma unroll
            for (int t = 0; t < 4; t++) acc[i][j][t] = 0.f;

#define LOAD_STAGE(buf, cc) do {                                              \
        int _kc = (cc) << 5;                                                  \
        uint32_t _dA = sbase + (buf) * (STAGE_ELEMS * 2);                     \
        uint32_t _dB = sbase + (NSTAGE + (buf)) * (STAGE_ELEMS * 2);          \
        _Pragma("unroll")                                                     \
        for (int _i = 0; _i < 2; ++_i) {                                      \
            int _c = tid + _i * 256;                                          \
            int _r = _c >> 2, _k8 = _c & 3;                                   \
            int _gr = row0 + _r; if (_gr >= M) _gr = M - 1;                   \
            CP_ASYNC16(_dA + (_r * PADS + _k8 * 8) * 2,                       \
                       A + (size_t)_gr * lda + _kc + _k8 * 8);                \
        }                                                                     \
        _Pragma("unroll")                                                     \
        for (int _i = 0; _i < 2; ++_i) {                                      \
            int _c = tid + _i * 256;                                          \
            int _r = _c >> 2, _k8 = _c & 3;                                   \
            CP_ASYNC16(_dB + (_r * PADS + _k8 * 8) * 2,                       \
                       B + (size_t)(col0 + _r) * ldb + _kc + _k8 * 8);        \
        }                                                                     \
    } while (0)

    LOAD_STAGE(0, 0);
    LOAD_STAGE(1, 1);
    CP_COMMIT();

    for (int c = 0; c < NC2; ++c) {
        CP_WAIT(0);
        __syncthreads();

        if (c + 1 < NC2) {
            const int pb = ((c + 1) & 1) << 1;
            LOAD_STAGE(pb, 2 * (c + 1));
            LOAD_STAGE(pb + 1, 2 * (c + 1) + 1);
        }
        CP_COMMIT();

        const int cb = (c & 1) << 1;
#pragma unroll
        for (int hs = 0; hs < 2; hs++) {
            const uint32_t baseA = sbase + (cb + hs) * (STAGE_ELEMS * 2);
            const uint32_t baseB = sbase + (NSTAGE + cb + hs) * (STAGE_ELEMS * 2);
#pragma unroll
            for (int kk = 0; kk < 32; kk += 16) {
                uint32_t a[2][4];
#pragma unroll
                for (int mt = 0; mt < 2; mt++) {
                    int r = wm * 32 + mt * 16 + (lane & 15);
                    int kc = kk + ((lane & 16) ? 8 : 0);
                    ldmatrix_x4(a[mt][0], a[mt][1], a[mt][2], a[mt][3],
                                baseA + (r * PADS + kc) * 2);
                }
                uint32_t b[8][2];
#pragma unroll
                for (int np = 0; np < 4; np++) {
                    int n = wn * 64 + np * 16 + (lane & 7) + ((lane & 16) ? 8 : 0);
                    int kc = kk + ((lane & 8) ? 8 : 0);
                    ldmatrix_x4(b[2 * np][0], b[2 * np][1], b[2 * np + 1][0], b[2 * np + 1][1],
                                baseB + (n * PADS + kc) * 2);
                }
#pragma unroll
                for (int mt = 0; mt < 2; mt++)
#pragma unroll
                    for (int nt = 0; nt < 8; nt++)
                        mma_f16(acc[mt][nt], a[mt], b[nt]);
            }
        }
    }

    // ---- epilogue ----
    if (mode == 2 && col0 < 256) {
        __syncthreads();
        __half* so = dynsmem;                  // [128][136]
#pragma unroll
        for (int mt = 0; mt < 2; mt++) {
#pragma unroll
            for (int hf = 0; hf < 2; hf++) {
                int r = wm * 32 + mt * 16 + (lane >> 2) + hf * 8;
#pragma unroll
                for (int nt = 0; nt < 8; nt++) {
                    int cc = wn * 64 + nt * 8 + (lane & 3) * 2;
                    float v0 = acc[mt][nt][hf * 2 + 0] + bias[col0 + cc];
                    float v1 = acc[mt][nt][hf * 2 + 1] + bias[col0 + cc + 1];
                    *reinterpret_cast<__half2*>(so + r * 136 + cc) = __floats2half2_rn(v0, v1);
                }
            }
        }
        __syncthreads();
#pragma unroll
        for (int h4 = 0; h4 < 4; h4++) {
            int head = (col0 >> 5) + h4;
            __half* dst = Ch + ((size_t)head * MTOK + row0) * 32;
#pragma unroll
            for (int it = 0; it < 2; it++) {
                int idx = tid * 2 + it;
                int r = idx >> 2;
                int cu = (idx & 3) * 8;
                if (row0 + r < M) {
                    const __half* sp = so + r * 136 + h4 * 32 + cu;
                    uint4 v;
                    v.x = *reinterpret_cast<const uint32_t*>(sp + 0);
                    v.y = *reinterpret_cast<const uint32_t*>(sp + 2);
                    v.z = *reinterpret_cast<const uint32_t*>(sp + 4);
                    v.w = *reinterpret_cast<const uint32_t*>(sp + 6);
                    *reinterpret_cast<uint4*>(dst + (size_t)r * 32 + cu) = v;
                }
            }
        }
        return;
    }

    float* outf = Cf;
    __half* outh = nullptr;
    int ostride = N, coff = 0;
    int write_half = 0;
    if (mode == 2) {
        if (col0 < 512) { outh = C2h; ostride = 256; coff = 256; write_half = 1; }
        else            { outf = C3;  ostride = 128; coff = 512; }
    }

#pragma unroll
    for (int mt = 0; mt < 2; mt++) {
#pragma unroll
        for (int half_i = 0; half_i < 2; half_i++) {
            int r = row0 + wm * 32 + mt * 16 + (lane >> 2) + half_i * 8;
            if (r >= M) continue;
#pragma unroll
            for (int nt = 0; nt < 8; nt++) {
                int cidx = col0 + wn * 64 + nt * 8 + (lane & 3) * 2;
                float v0 = acc[mt][nt][half_i * 2 + 0] + bias[cidx];
                float v1 = acc[mt][nt][half_i * 2 + 1] + bias[cidx + 1];
                if (relu) { v0 = fmaxf(v0, 0.f); v1 = fmaxf(v1, 0.f); }
                if (write_half) {
                    __half2 hv;
                    hv.x = __float2half_rn(v0);
                    hv.y = __float2half_rn(v1);
                    *reinterpret_cast<__half2*>(outh + (size_t)r * ostride + (cidx - coff)) = hv;
                } else {
                    float2 o = make_float2(v0, v1);
                    *reinterpret_cast<float2*>(outf + (size_t)r * ostride + (cidx - coff)) = o;
                }
            }
        }
    }
#undef LOAD_STAGE
}

// ---------------- GEMM + residual(fp16) + LayerNorm fused (N = 256) --------
#define A_ST (128 * PADS * 2)
#define B_ST (256 * PADS * 2)
#define GEMMLN_SMEM (NSTAGE * (A_ST + B_ST))   // 122880 bytes

__global__ __launch_bounds__(512, 1)
void gemm_ln(const __half* __restrict__ A, int lda,
             const __half* __restrict__ B,
             const float* __restrict__ bias,
             const __half* __restrict__ resid,
             const float* __restrict__ lng, const float* __restrict__ lnb,
             float* __restrict__ out, __half* __restrict__ outh,
             int M, int K)
{
    extern __shared__ __align__(16) __half dynsmem[];

    const int tid  = threadIdx.x;
    const int wid  = tid >> 5;
    const int lane = tid & 31;
    const int wm   = wid & 3;
    const int wn   = wid >> 2;
    const int row0 = blockIdx.y * 128;

    const uint32_t sbase = smem_u32(dynsmem);
    const uint32_t sbB = sbase + NSTAGE * A_ST;
    const int NC2 = K >> 6;

    float acc[2][8][4];
#pragma unroll
    for (int i = 0; i < 2; i++)
#pragma unroll
        for (int j = 0; j < 8; j++)
#pragma unroll
            for (int t = 0; t < 4; t++) acc[i][j][t] = 0.f;

#define LOAD_STAGE_LN(buf, cc) do {                                           \
        int _kc = (cc) << 5;                                                  \
        uint32_t _dA = sbase + (buf) * A_ST;                                  \
        uint32_t _dB = sbB + (buf) * B_ST;                                    \
        {                                                                     \
            int _r = tid >> 2, _k8 = tid & 3;                                 \
            int _gr = row0 + _r; if (_gr >= M) _gr = M - 1;                   \
            CP_ASYNC16(_dA + (_r * PADS + _k8 * 8) * 2,                       \
                       A + (size_t)_gr * lda + _kc + _k8 * 8);                \
        }                                                                     \
        _Pragma("unroll")                                                     \
        for (int _i = 0; _i < 2; ++_i) {                                      \
            int _c = tid + _i * 512;                                          \
            int _r = _c >> 2, _k8 = _c & 3;                                   \
            CP_ASYNC16(_dB + (_r * PADS + _k8 * 8) * 2,                       \
                       B + (size_t)_r * K + _kc + _k8 * 8);                   \
        }                                                                     \
    } while (0)

    LOAD_STAGE_LN(0, 0);
    LOAD_STAGE_LN(1, 1);
    CP_COMMIT();

    for (int c = 0; c < NC2; ++c) {
        CP_WAIT(0);
        __syncthreads();

        if (c + 1 < NC2) {
            const int pb = ((c + 1) & 1) << 1;
            LOAD_STAGE_LN(pb, 2 * (c + 1));
            LOAD_STAGE_LN(pb + 1, 2 * (c + 1) + 1);
        }
        CP_COMMIT();

        const int cb = (c & 1) << 1;
#pragma unroll
        for (int hs = 0; hs < 2; hs++) {
            const uint32_t baseA = sbase + (cb + hs) * A_ST;
            const uint32_t baseB = sbB + (cb + hs) * B_ST;
#pragma unroll
            for (int kk = 0; kk < 32; kk += 16) {
                uint32_t a[2][4];
#pragma unroll
                for (int mt = 0; mt < 2; mt++) {
                    int r = wm * 32 + mt * 16 + (lane & 15);
                    int kc = kk + ((lane & 16) ? 8 : 0);
                    ldmatrix_x4(a[mt][0], a[mt][1], a[mt][2], a[mt][3],
                                baseA + (r * PADS + kc) * 2);
                }
                uint32_t b[8][2];
#pragma unroll
                for (int np = 0; np < 4; np++) {
                    int n = wn * 64 + np * 16 + (lane & 7) + ((lane & 16) ? 8 : 0);
                    int kc = kk + ((lane & 8) ? 8 : 0);
                    ldmatrix_x4(b[2 * np][0], b[2 * np][1], b[2 * np + 1][0], b[2 * np + 1][1],
                                baseB + (n * PADS + kc) * 2);
                }
#pragma unroll
                for (int mt = 0; mt < 2; mt++)
#pragma unroll
                    for (int nt = 0; nt < 8; nt++)
                        mma_f16(acc[mt][nt], a[mt], b[nt]);
            }
        }
    }

    __syncthreads();
    float* red = reinterpret_cast<float*>(dynsmem);

#pragma unroll
    for (int mt = 0; mt < 2; mt++) {
#pragma unroll
        for (int hf = 0; hf < 2; hf++) {
            int lr = wm * 32 + mt * 16 + (lane >> 2) + hf * 8;
            int r = row0 + lr;
            int rc = (r < M) ? r : (M - 1);
            float s1 = 0.f, s2 = 0.f;
#pragma unroll
            for (int nt = 0; nt < 8; nt++) {
                int cidx = wn * 64 + nt * 8 + (lane & 3) * 2;
                __half2 rh = *reinterpret_cast<const __half2*>(resid + (size_t)rc * 256 + cidx);
                float2 res = __half22float2(rh);
                float2 bv = *reinterpret_cast<const float2*>(bias + cidx);
                float v0 = acc[mt][nt][hf * 2 + 0] + bv.x + res.x;
                float v1 = acc[mt][nt][hf * 2 + 1] + bv.y + res.y;
                acc[mt][nt][hf * 2 + 0] = v0;
                acc[mt][nt][hf * 2 + 1] = v1;
                s1 += v0 + v1;
                s2 += v0 * v0 + v1 * v1;
            }
            s1 += __shfl_xor_sync(0xffffffffu, s1, 1);
            s2 += __shfl_xor_sync(0xffffffffu, s2, 1);
            s1 += __shfl_xor_sync(0xffffffffu, s1, 2);
            s2 += __shfl_xor_sync(0xffffffffu, s2, 2);
            if ((lane & 3) == 0) {
                red[(wn * 128 + lr) * 2 + 0] = s1;
                red[(wn * 128 + lr) * 2 + 1] = s2;
            }
        }
    }
    __syncthreads();

#pragma unroll
    for (int mt = 0; mt < 2; mt++) {
#pragma unroll
        for (int hf = 0; hf < 2; hf++) {
            int lr = wm * 32 + mt * 16 + (lane >> 2) + hf * 8;
            int r = row0 + lr;
            if (r >= M) continue;
            float t1 = red[(0 * 128 + lr) * 2 + 0] + red[(1 * 128 + lr) * 2 + 0]
                     + red[(2 * 128 + lr) * 2 + 0] + red[(3 * 128 + lr) * 2 + 0];
            float t2 = red[(0 * 128 + lr) * 2 + 1] + red[(1 * 128 + lr) * 2 + 1]
                     + red[(2 * 128 + lr) * 2 + 1] + red[(3 * 128 + lr) * 2 + 1];
            float mean = t1 * (1.f / 256.f);
            float var = t2 * (1.f / 256.f) - mean * mean;
            float inv = rsqrtf(var + 1e-5f);
#pragma unroll
            for (int nt = 0; nt < 8; nt++) {
                int cidx = wn * 64 + nt * 8 + (lane & 3) * 2;
                float2 gv = *reinterpret_cast<const float2*>(lng + cidx);
                float2 bv = *reinterpret_cast<const float2*>(lnb + cidx);
                float o0 = (acc[mt][nt][hf * 2 + 0] - mean) * inv * gv.x + bv.x;
                float o1 = (acc[mt][nt][hf * 2 + 1] - mean) * inv * gv.y + bv.y;
                if (out)
                    *reinterpret_cast<float2*>(out + (size_t)r * 256 + cidx) = make_float2(o0, o1);
                if (outh) {
                    __half2 hv;
                    hv.x = __float2half_rn(o0);
                    hv.y = __float2half_rn(o1);
                    *reinterpret_cast<__half2*>(outh + (size_t)r * 256 + cidx) = hv;
                }
            }
        }
    }
#undef LOAD_STAGE_LN
}

// ================= fused MLP + LN2: out = LN(x + relu(x@W1+b1)@W2 + b2) ====
// 512 threads / 16 warps, 128 rows per CTA, h kept in smem (8 DFF chunks).
// smem (halfs): XS 40960 | W1B 2x5120 | HS 4x5120 | W2B 2x10240 = 92160 halfs.
#define MLP_XS   0
#define MLP_W1B  40960
#define MLP_HS   51200
#define MLP_W2B  71680
#define MLP_SMEM (92160 * 2)   // 184320 bytes

__global__ __launch_bounds__(512, 1)
void mlp_ln(const __half* __restrict__ X,
            const __half* __restrict__ W1, const float* __restrict__ b1,
            const __half* __restrict__ W2, const float* __restrict__ b2,
            const float* __restrict__ lng, const float* __restrict__ lnb,
            float* __restrict__ out, int M)
{
    extern __shared__ __align__(16) __half dynsmem[];

    const int tid  = threadIdx.x;
    const int wid  = tid >> 5;
    const int lane = tid & 31;
    const int row0 = blockIdx.x * 128;

    const uint32_t sb = smem_u32(dynsmem);
    const uint32_t sXS  = sb + MLP_XS * 2;
    const uint32_t sW1B = sb + MLP_W1B * 2;
    const uint32_t sHS  = sb + MLP_HS * 2;
    const uint32_t sW2B = sb + MLP_W2B * 2;

    // phase-1 warp mapping: 4x4 (32-row x 32-col), phase-2: 4x4 (32-row x 64-col)
    const int wm = wid & 3;
    const int wn4 = wid >> 2;   // 0..3

    // ---- preload: x tile (8 subchunks) + W1 chunk0 sub0 ----
    {
        int r = tid >> 2, k8 = tid & 3;
        int gr = row0 + r; if (gr >= M) gr = M - 1;
#pragma unroll
        for (int ks = 0; ks < 8; ks++)
            CP_ASYNC16(sXS + (ks * 5120 + r * PADS + k8 * 8) * 2,
                       X + (size_t)gr * 256 + ks * 32 + k8 * 8);
        // W1 (chunk 0, sub 0): rows 0..127 of W1, k 0..31
        CP_ASYNC16(sW1B + (r * PADS + k8 * 8) * 2,
                   W1 + (size_t)r * 256 + k8 * 8);
    }
    CP_COMMIT();

    float acc2[2][8][4];
#pragma unroll
    for (int i = 0; i < 2; i++)
#pragma unroll
        for (int j = 0; j < 8; j++)
#pragma unroll
            for (int t = 0; t < 4; t++) acc2[i][j][t] = 0.f;

    for (int c = 0; c < 8; ++c) {
        float acc1[2][4][4];
#pragma unroll
        for (int i = 0; i < 2; i++)
#pragma unroll
            for (int j = 0; j < 4; j++)
#pragma unroll
                for (int t = 0; t < 4; t++) acc1[i][j][t] = 0.f;

        // ---- phase 1: acc1 = x @ W1_c^T over 8 K-subchunks ----
        for (int ks = 0; ks < 8; ++ks) {
            CP_WAIT(0);
            __syncthreads();
            // prefetch next W1 sub, or first W2 sub of this chunk
            if (ks < 7) {
                int r = tid >> 2, k8 = tid & 3;
                CP_ASYNC16(sW1B + (((ks + 1) & 1) * 5120 + r * PADS + k8 * 8) * 2,
                           W1 + (size_t)(c * 128 + r) * 256 + (ks + 1) * 32 + k8 * 8);
            } else {
                // W2 (chunk c, sub 0): 256 rows x 32 k
#pragma unroll
                for (int i = 0; i < 2; i++) {
                    int idx = tid + i * 512;
                    int r = idx >> 2, k8 = idx & 3;
                    CP_ASYNC16(sW2B + (r * PADS + k8 * 8) * 2,
                               W2 + (size_t)r * 1024 + c * 128 + k8 * 8);
                }
            }
            CP_COMMIT();

            const uint32_t baseA = sXS + ks * 5120 * 2;
            const uint32_t baseB = sW1B + (ks & 1) * 5120 * 2;
#pragma unroll
            for (int kk = 0; kk < 32; kk += 16) {
                uint32_t a[2][4];
#pragma unroll
                for (int mt = 0; mt < 2; mt++) {
                    int r = wm * 32 + mt * 16 + (lane & 15);
                    int kc = kk + ((lane & 16) ? 8 : 0);
                    ldmatrix_x4(a[mt][0], a[mt][1], a[mt][2], a[mt][3],
                                baseA + (r * PADS + kc) * 2);
                }
                uint32_t b[4][2];
#pragma unroll
                for (int np = 0; np < 2; np++) {
                    int n = wn4 * 32 + np * 16 + (lane & 7) + ((lane & 16) ? 8 : 0);
                    int kc = kk + ((lane & 8) ? 8 : 0);
                    ldmatrix_x4(b[2 * np][0], b[2 * np][1], b[2 * np + 1][0], b[2 * np + 1][1],
                                baseB + (n * PADS + kc) * 2);
                }
#pragma unroll
                for (int mt = 0; mt < 2; mt++)
#pragma unroll
                    for (int nt = 0; nt < 4; nt++)
                        mma_f16(acc1[mt][nt], a[mt], b[nt]);
            }
        }

        // ---- h = relu(acc1 + b1) -> smem (ldmatrix layout, K-sub PADS) ----
        // safe: hs last read in phase 2 of chunk c-1, before this chunk's syncs
#pragma unroll
        for (int mt = 0; mt < 2; mt++) {
#pragma unroll
            for (int hf = 0; hf < 2; hf++) {
                int r = wm * 32 + mt * 16 + (lane >> 2) + hf * 8;
#pragma unroll
                for (int nt = 0; nt < 4; nt++) {
                    int cc = wn4 * 32 + nt * 8 + (lane & 3) * 2;   // 0..127
                    float v0 = fmaxf(acc1[mt][nt][hf * 2 + 0] + b1[c * 128 + cc], 0.f);
                    float v1 = fmaxf(acc1[mt][nt][hf * 2 + 1] + b1[c * 128 + cc + 1], 0.f);
                    uint32_t addr = sHS + (((cc >> 5) * 5120) + r * PADS + (cc & 31)) * 2;
                    __half2 hv = __floats2half2_rn(v0, v1);
                    *reinterpret_cast<__half2*>(dynsmem + (addr - sb) / 2) = hv;
                }
            }
        }
        __syncthreads();   // hs visible

        // ---- phase 2: acc2 += h @ W2_c^T over 4 K-subchunks ----
        for (int kh = 0; kh < 4; ++kh) {
            CP_WAIT(0);
            __syncthreads();
            if (kh < 3) {
#pragma unroll
                for (int i = 0; i < 2; i++) {
                    int idx = tid + i * 512;
                    int r = idx >> 2, k8 = idx & 3;
                    CP_ASYNC16(sW2B + (((kh + 1) & 1) * 10240 + r * PADS + k8 * 8) * 2,
                               W2 + (size_t)r * 1024 + c * 128 + (kh + 1) * 32 + k8 * 8);
                }
            } else if (c < 7) {
                int r = tid >> 2, k8 = tid & 3;
                CP_ASYNC16(sW1B + (r * PADS + k8 * 8) * 2,
                           W1 + (size_t)((c + 1) * 128 + r) * 256 + k8 * 8);
            }
            CP_COMMIT();

            const uint32_t baseA = sHS + kh * 5120 * 2;
            const uint32_t baseB = sW2B + (kh & 1) * 10240 * 2;
#pragma unroll
            for (int kk = 0; kk < 32; kk += 16) {
                uint32_t a[2][4];
#pragma unroll
                for (int mt = 0; mt < 2; mt++) {
                    int r = wm * 32 + mt * 16 + (lane & 15);
                    int kc = kk + ((lane & 16) ? 8 : 0);
                    ldmatrix_x4(a[mt][0], a[mt][1], a[mt][2], a[mt][3],
                                baseA + (r * PADS + kc) * 2);
                }
                uint32_t b[8][2];
#pragma unroll
                for (int np = 0; np < 4; np++) {
                    int n = wn4 * 64 + np * 16 + (lane & 7) + ((lane & 16) ? 8 : 0);
                    int kc = kk + ((lane & 8) ? 8 : 0);
                    ldmatrix_x4(b[2 * np][0], b[2 * np][1], b[2 * np + 1][0], b[2 * np + 1][1],
                                baseB + (n * PADS + kc) * 2);
                }
#pragma unroll
                for (int mt = 0; mt < 2; mt++)
#pragma unroll
                    for (int nt = 0; nt < 8; nt++)
                        mma_f16(acc2[mt][nt], a[mt], b[nt]);
            }
        }
    }

    // ---- LN2 epilogue: out = LN(x + acc2 + b2) ----
    CP_WAIT(0);
    __syncthreads();
    float* red = reinterpret_cast<float*>(dynsmem);

#pragma unroll
    for (int mt = 0; mt < 2; mt++) {
#pragma unroll
        for (int hf = 0; hf < 2; hf++) {
            int lr = wm * 32 + mt * 16 + (lane >> 2) + hf * 8;
            int r = row0 + lr;
            int rc = (r < M) ? r : (M - 1);
            float s1 = 0.f, s2 = 0.f;
#pragma unroll
            for (int nt = 0; nt < 8; nt++) {
                int cidx = wn4 * 64 + nt * 8 + (lane & 3) * 2;
                __half2 rh = *reinterpret_cast<const __half2*>(X + (size_t)rc * 256 + cidx);
                float2 res = __half22float2(rh);
                float2 bv = *reinterpret_cast<const float2*>(b2 + cidx);
                float v0 = acc2[mt][nt][hf * 2 + 0] + bv.x + res.x;
                float v1 = acc2[mt][nt][hf * 2 + 1] + bv.y + res.y;
                acc2[mt][nt][hf * 2 + 0] = v0;
                acc2[mt][nt][hf * 2 + 1] = v1;
                s1 += v0 + v1;
                s2 += v0 * v0 + v1 * v1;
            }
            s1 += __shfl_xor_sync(0xffffffffu, s1, 1);
            s2 += __shfl_xor_sync(0xffffffffu, s2, 1);
            s1 += __shfl_xor_sync(0xffffffffu, s1, 2);
            s2 += __shfl_xor_sync(0xffffffffu, s2, 2);
            if ((lane & 3) == 0) {
                red[(wn4 * 128 + lr) * 2 + 0] = s1;
                red[(wn4 * 128 + lr) * 2 + 1] = s2;
            }
        }
    }
    __syncthreads();

#pragma unroll
    for (int mt = 0; mt < 2; mt++) {
#pragma unroll
        for (int hf = 0; hf < 2; hf++) {
            int lr = wm * 32 + mt * 16 + (lane >> 2) + hf * 8;
            int r = row0 + lr;
            if (r >= M) continue;
            float t1 = red[(0 * 128 + lr) * 2 + 0] + red[(1 * 128 + lr) * 2 + 0]
                     + red[(2 * 128 + lr) * 2 + 0] + red[(3 * 128 + lr) * 2 + 0];
            float t2 = red[(0 * 128 + lr) * 2 + 1] + red[(1 * 128 + lr) * 2 + 1]
                     + red[(2 * 128 + lr) * 2 + 1] + red[(3 * 128 + lr) * 2 + 1];
            float mean = t1 * (1.f / 256.f);
            float var = t2 * (1.f / 256.f) - mean * mean;
            float inv = rsqrtf(var + 1e-5f);
#pragma unroll
            for (int nt = 0; nt < 8; nt++) {
                int cidx = wn4 * 64 + nt * 8 + (lane & 3) * 2;
                float2 gv = *reinterpret_cast<const float2*>(lng + cidx);
                float2 bv = *reinterpret_cast<const float2*>(lnb + cidx);
                float o0 = (acc2[mt][nt][hf * 2 + 0] - mean) * inv * gv.x + bv.x;
                float o1 = (acc2[mt][nt][hf * 2 + 1] - mean) * inv * gv.y + bv.y;
                *reinterpret_cast<float2*>(out + (size_t)r * 256 + cidx) = make_float2(o0, o1);
            }
        }
    }
}

// ---------------- fused weight prep + qh = fp16(src + pos) -----------------
__device__ __forceinline__ void wtr1(const float* __restrict__ W, __half* __restrict__ Wt,
                                     int K_, int N_, int i)
{
    int k = i / N_, n = i % N_;
    Wt[(size_t)n * K_ + k] = __float2half_rn(W[i]);
}

#define PREP_ITEMS 754304
#define ADD_ITEMS  (MTOK * DMODEL / 4)
#define PA_TOTAL   (PREP_ITEMS + ADD_ITEMS)

__global__ void prep_add_kernel(const float* __restrict__ vW, const float* __restrict__ oW,
                                const float* __restrict__ aW, const float* __restrict__ uW,
                                const float* __restrict__ f1W, const float* __restrict__ f2W,
                                const float* __restrict__ vb, const float* __restrict__ ob,
                                const float* __restrict__ ab,
                                __half* __restrict__ wtp, __half* __restrict__ wtu,
                                __half* __restrict__ wtf1, __half* __restrict__ wtf2,
                                float* __restrict__ biasp,
                                const float* __restrict__ srca, const float* __restrict__ posb,
                                __half* __restrict__ qh)
{
    int i = blockIdx.x * blockDim.x + threadIdx.x;
    if (i >= PREP_ITEMS) {
        int t = i - PREP_ITEMS;
        if (t >= ADD_ITEMS) return;
        float4 x = reinterpret_cast<const float4*>(srca)[t];
        float4 y = reinterpret_cast<const float4*>(posb)[t];
        x.x += y.x; x.y += y.y; x.z += y.z; x.w += y.w;
        __half2 h0 = __floats2half2_rn(x.x, x.y);
        __half2 h1 = __floats2half2_rn(x.z, x.w);
        uint2 hp;
        hp.x = *reinterpret_cast<uint32_t*>(&h0);
        hp.y = *reinterpret_cast<uint32_t*>(&h1);
        reinterpret_cast<uint2*>(qh)[t] = hp;
        return;
    }
    if (i < 65536)       { wtr1(vW, wtp, 256, 256, i); return; }
    i -= 65536;
    if (i < 65536)       { wtr1(oW, wtp + 256 * 256, 256, 256, i); return; }
    i -= 65536;
    if (i < 32768)       { wtr1(aW, wtp + 512 * 256, 256, 128, i); return; }
    i -= 32768;
    if (i < 65536)       { wtr1(uW, wtu, 256, 256, i); return; }
    i -= 65536;
    if (i < 262144)      { wtr1(f1W, wtf1, 256, 1024, i); return; }
    i -= 262144;
    if (i < 262144)      { wtr1(f2W, wtf2, 1024, 256, i); return; }
    i -= 262144;
    if (i < 256)         { biasp[i] = vb[i]; return; }
    if (i < 512)         { biasp[i] = ob[i - 256]; return; }
    if (i < 640)         { biasp[i] = ab[i - 512]; return; }
}

// ---------------- MSDA v4: paired-corner coalesced gathers -----------------
__global__ __launch_bounds__(256)
void msda_kernel(const __half* __restrict__ value, const __half* __restrict__ offs,
                 const float* __restrict__ aw, const float* __restrict__ ref,
                 const int* __restrict__ shapes, const int* __restrict__ starts,
                 __half* __restrict__ outh)
{
    const int tok = blockIdx.x;
    const int h = threadIdx.x >> 5;
    const int lane = threadIdx.x & 31;
    const int j = lane & 15;
    const int hi = lane >> 4;
    const int b = tok / LIN;
    const int l = j >> 2;

    const int Hl = shapes[l * 2 + 0];
    const int Wl = shapes[l * 2 + 1];
    const int st = starts[l];
    const float fW = (float)Wl, fH = (float)Hl;
    const float rx = ref[(size_t)tok * 8 + l * 2 + 0];
    const float ry = ref[(size_t)tok * 8 + l * 2 + 1];
    __half2 offh = *reinterpret_cast<const __half2*>(offs + (size_t)tok * 256 + h * 32 + 2 * j);
    float2 off = __half22float2(offh);

    float logit = aw[(size_t)tok * 128 + h * 16 + j];
    float m = logit;
#pragma unroll
    for (int o = 8; o; o >>= 1) m = fmaxf(m, __shfl_xor_sync(0xffffffffu, m, o, 16));
    float e = expf(logit - m);
    float s = e;
#pragma unroll
    for (int o = 8; o; o >>= 1) s += __shfl_xor_sync(0xffffffffu, s, o, 16);
    float wgt = e / s;

    float x = (rx + off.x / fW) * fW - 0.5f;
    float y = (ry + off.y / fH) * fH - 0.5f;
    float x0f = floorf(x), y0f = floorf(y);
    float dx = x - x0f, dy = y - y0f;
    int x0 = (int)x0f, y0 = (int)y0f;
    int x1 = x0 + 1, y1 = y0 + 1;

    bool xv0 = (x0 >= 0) & (x0 < Wl);
    bool xv1 = (x1 >= 0) & (x1 < Wl);
    bool yv0 = (y0 >= 0) & (y0 < Hl);
    bool yv1 = (y1 >= 0) & (y1 < Hl);

    float w00 = (xv0 && yv0) ? wgt * (1.f - dx) * (1.f - dy) : 0.f;
    float w10 = (xv1 && yv0) ? wgt * dx * (1.f - dy) : 0.f;
    float w01 = (xv0 && yv1) ? wgt * (1.f - dx) * dy : 0.f;
    float w11 = (xv1 && yv1) ? wgt * dx * dy : 0.f;

    int cx0 = min(max(x0, 0), Wl - 1), cx1 = min(max(x1, 0), Wl - 1);
    int cy0 = min(max(y0, 0), Hl - 1), cy1 = min(max(y1, 0), Hl - 1);
    const int base = b * LIN + st;
    int ixy0 = base + cy0 * Wl + (hi ? cx1 : cx0);
    int ixy1 = base + cy1 * Wl + (hi ? cx1 : cx0);
    float uwy0 = hi ? w10 : w00;
    float uwy1 = hi ? w11 : w01;

    const int pg  = lane >> 3;
    const int sel = (lane >> 2) & 1;
    const int c4  = lane & 3;
    const __half* vch = value + (size_t)h * MTOK * 32 + c4 * 8;
    float acc[8] = {0.f, 0.f, 0.f, 0.f, 0.f, 0.f, 0.f, 0.f};

#pragma unroll
    for (int p = 0; p < 4; p++) {
        const int pt = p * 4 + pg;
        const int srcl = pt + (sel << 4);
        int ay = __shfl_sync(0xffffffffu, ixy0, srcl);
        int by = __shfl_sync(0xffffffffu, ixy1, srcl);
        float uy = __shfl_sync(0xffffffffu, uwy0, srcl);
        float vy = __shfl_sync(0xffffffffu, uwy1, srcl);

        uint4 r0 = *reinterpret_cast<const uint4*>(vch + (size_t)ay * 32);
        uint4 r1 = *reinterpret_cast<const uint4*>(vch + (size_t)by * 32);

#define ACC8(rv, u) do {                                                      \
        const __half2* _h = reinterpret_cast<const __half2*>(&(rv));          \
        _Pragma("unroll")                                                     \
        for (int _k = 0; _k < 4; _k++) {                                      \
            float2 _f = __half22float2(_h[_k]);                               \
            acc[2 * _k + 0] = fmaf(u, _f.x, acc[2 * _k + 0]);                 \
            acc[2 * _k + 1] = fmaf(u, _f.y, acc[2 * _k + 1]);                 \
        } } while (0)

        ACC8(r0, uy);
        ACC8(r1, vy);
#undef ACC8
    }

#pragma unroll
    for (int o = 4; o <= 16; o <<= 1) {
#pragma unroll
        for (int k = 0; k < 8; k++)
            acc[k] += __shfl_xor_sync(0xffffffffu, acc[k], o);
    }

    if (lane < 4) {
        __half2 h0 = __floats2half2_rn(acc[0], acc[1]);
        __half2 h1 = __floats2half2_rn(acc[2], acc[3]);
        __half2 h2 = __floats2half2_rn(acc[4], acc[5]);
        __half2 h3 = __floats2half2_rn(acc[6], acc[7]);
        uint4 o;
        o.x = *reinterpret_cast<uint32_t*>(&h0);
        o.y = *reinterpret_cast<uint32_t*>(&h1);
        o.z = *reinterpret_cast<uint32_t*>(&h2);
        o.w = *reinterpret_cast<uint32_t*>(&h3);
        *reinterpret_cast<uint4*>(outh + (size_t)tok * DMODEL + h * DH + lane * 8) = o;
    }
}

// ---------------- launch ----------------
extern "C" void kernel_launch(void* const* d_in, const int* in_sizes, int n_in,
                              void* d_out, int out_size)
{
    const float* src    = (const float*)d_in[0];
    const float* pos    = (const float*)d_in[1];
    const float* refpts = (const float*)d_in[2];
    const int*   shapes = (const int*)  d_in[3];
    const int*   starts = (const int*)  d_in[4];
    const float* value_w = (const float*)d_in[5];
    const float* value_b = (const float*)d_in[6];
    const float* offs_w  = (const float*)d_in[7];
    const float* offs_b  = (const float*)d_in[8];
    const float* attn_w  = (const float*)d_in[9];
    const float* attn_b  = (const float*)d_in[10];
    const float* out_w   = (const float*)d_in[11];
    const float* out_b   = (const float*)d_in[12];
    const float* ln1_g   = (const float*)d_in[13];
    const float* ln1_b   = (const float*)d_in[14];
    const float* ff1_w   = (const float*)d_in[15];
    const float* ff1_b   = (const float*)d_in[16];
    const float* ff2_w   = (const float*)d_in[17];
    const float* ff2_b   = (const float*)d_in[18];
    const float* ln2_g   = (const float*)d_in[19];
    const float* ln2_b   = (const float*)d_in[20];
    float* outp = (float*)d_out;

    float *aw, *biasp;
    __half *qh, *value, *offs, *msdah, *xh;
    __half *wtp, *wtu, *wtf1, *wtf2;
    cudaGetSymbolAddress((void**)&qh,    g_qh);
    cudaGetSymbolAddress((void**)&value, g_value);
    cudaGetSymbolAddress((void**)&offs,  g_offs);
    cudaGetSymbolAddress((void**)&aw,    g_aw);
    cudaGetSymbolAddress((void**)&msdah, g_msdah);
    cudaGetSymbolAddress((void**)&xh,    g_xh);
    cudaGetSymbolAddress((void**)&wtp,   g_wt_proj);
    cudaGetSymbolAddress((void**)&wtu,   g_wt_out);
    cudaGetSymbolAddress((void**)&wtf1,  g_wt_ff1);
    cudaGetSymbolAddress((void**)&wtf2,  g_wt_ff2);
    cudaGetSymbolAddress((void**)&biasp, g_bias_proj);

    cudaFuncSetAttribute(gemm_mma, cudaFuncAttributeMaxDynamicSharedMemorySize, GEMM_SMEM);
    cudaFuncSetAttribute(gemm_ln, cudaFuncAttributeMaxDynamicSharedMemorySize, GEMMLN_SMEM);
    cudaFuncSetAttribute(mlp_ln, cudaFuncAttributeMaxDynamicSharedMemorySize, MLP_SMEM);

    const int M = MTOK;
    const int gy = (M + 127) / 128;

    // 0. fused weight prep + qh = fp16(src + pos)
    prep_add_kernel<<<(PA_TOTAL + 255) / 256, 256>>>(value_w, offs_w, attn_w, out_w, ff1_w, ff2_w,
                                                     value_b, offs_b, attn_b,
                                                     wtp, wtu, wtf1, wtf2, biasp,
                                                     src, pos, qh);

    // 1. fused projections: [value(fp16, transposed) | offs(fp16) | aw(fp32)]
    gemm_mma<<<dim3(5, gy), 256, GEMM_SMEM>>>(qh, 256, wtp, 256, biasp,
                                              nullptr, value, offs, aw, M, 256, 640, 0, 2);

    // 2. deformable sampling with fused softmax (paired-corner gathers)
    msda_kernel<<<M, 256>>>(value, offs, aw, refpts, shapes, starts, msdah);

    // 3. xh = fp16(LN(qh + msda @ out_w + out_b))   [fused GEMM+LN]
    gemm_ln<<<dim3(1, gy), 512, GEMMLN_SMEM>>>(msdah, 256, wtu, out_b,
                                               qh, ln1_g, ln1_b, nullptr, xh, M, 256);

    // 4. out = LN(xh + relu(xh@W1+b1)@W2 + b2)   [fully fused MLP + LN2]
    mlp_ln<<<gy, 512, MLP_SMEM>>>(xh, wtf1, ff1_b, wtf2, ff2_b,
                                  ln2_g, ln2_b, outp, M);
}